// round 13
// baseline (speedup 1.0000x reference)
#include <cuda_runtime.h>
#include <cuda_bf16.h>
#include <math.h>

#define NPTS  32768
#define NQ    4096
#define BATCH 2
#define KNBR  32
#define EMBD  96
#define C0    128
#define C1    256

typedef unsigned int u32;
typedef unsigned short u16;

// ---------------- global scratch (no allocation allowed) ----------------
__device__ float g_A[BATCH * NPTS * C0];
__device__ float g_Px[NQ * C0];             // batch-independent (bbox == [0,1]^3)
// W1 images: [n=256][k=128] pitch 136 halves (272B)
__device__ __align__(16) u16 g_W1i_hi[256 * 136];
__device__ __align__(16) u16 g_W1i_lo[256 * 136];
// W2 images split by k-half: [khalf=2][n=128][k'=128] pitch 136 halves
__device__ __align__(16) u16 g_W2i_hi[2 * 128 * 136];
__device__ __align__(16) u16 g_W2i_lo[2 * 128 * 136];

__constant__ float c_freq[16] = {
    1.0f, 0.562341325190349f, 0.316227766016838f, 0.177827941003892f,
    0.1f, 0.0562341325190349f, 0.0316227766016838f, 0.0177827941003892f,
    0.01f, 0.00562341325190349f, 0.00316227766016838f, 0.00177827941003892f,
    0.001f, 0.000562341325190349f, 0.000316227766016838f, 0.000177827941003892f };

// pitches (bytes)
#define PB1 272     // A1/W1/W2half rows: 136 halves
#define PB2 528     // A2 rows: 264 halves
#define PH2 132     // h2 floats pitch

// smem regions (bytes from aligned base), M=64 plan, peak 104448
#define OFF_A1HI 0            // 64*272 = 17408
#define OFF_A1LO 17408        // end 34816
#define OFF_W1   34816        // 256*272 = 69632, end 104448 (single image buf)
#define OFF_A2HI 0            // 64*528 = 33792
#define OFF_A2LO 33792        // end 67584
#define OFF_W2   67584        // 128*272 = 34816, end 102400 (single image buf)
#define OFF_H2   0            // 64*132*4 = 33792
#define DSM_BYTES (104448 + 128)

static __device__ __forceinline__ u32 smem_u32(const void* p) {
    u32 a; asm("{ .reg .u64 t; cvta.to.shared.u64 t, %1; cvt.u32.u64 %0, t; }" : "=r"(a) : "l"(p));
    return a;
}
__device__ __forceinline__ void ldsm_x4(u32* r, u32 addr) {
    asm volatile("ldmatrix.sync.aligned.m8n8.x4.shared.b16 {%0,%1,%2,%3}, [%4];"
        : "=r"(r[0]), "=r"(r[1]), "=r"(r[2]), "=r"(r[3]) : "r"(addr));
}
__device__ __forceinline__ void mma16816(float* c, const u32* a, const u32* b) {
    asm volatile("mma.sync.aligned.m16n8k16.row.col.f32.bf16.bf16.f32 "
        "{%0,%1,%2,%3}, {%4,%5,%6,%7}, {%8,%9}, {%0,%1,%2,%3};"
        : "+f"(c[0]), "+f"(c[1]), "+f"(c[2]), "+f"(c[3])
        : "r"(a[0]), "r"(a[1]), "r"(a[2]), "r"(a[3]), "r"(b[0]), "r"(b[1]));
}
__device__ __forceinline__ float gelu_fast(float x) {
    float z = 1.5957691216057308f * (x + 0.044715f * x * x * x);
    return x * __frcp_rn(1.0f + __expf(-z));
}
__device__ __forceinline__ void split_pack(float v0, float v1, u32& hi, u32& lo) {
    __nv_bfloat16 h0 = __float2bfloat16(v0), h1 = __float2bfloat16(v1);
    float r0 = v0 - __bfloat162float(h0), r1 = v1 - __bfloat162float(h1);
    __nv_bfloat16 l0 = __float2bfloat16(r0), l1 = __float2bfloat16(r1);
    hi = (u32)__bfloat16_as_ushort(h0) | ((u32)__bfloat16_as_ushort(h1) << 16);
    lo = (u32)__bfloat16_as_ushort(l0) | ((u32)__bfloat16_as_ushort(l1) << 16);
}

// ---------------------------------------------------------------------------
// prep: blocks [0,512) wpack | [512,640) px | [640,2688) a   (same as R12)
// ---------------------------------------------------------------------------
__global__ void __launch_bounds__(128) prep_kernel(const float* __restrict__ x,
                                                   const float* __restrict__ gc,
                                                   const float* __restrict__ latent,
                                                   const float* __restrict__ W0,
                                                   const float* __restrict__ b0,
                                                   const float* __restrict__ W1,
                                                   const float* __restrict__ W2) {
    int blk = blockIdx.x;
    int t = threadIdx.x;

    if (blk < 512) {                                // ---- wpack ----
        int i = blk * 128 + t;
        if (i < 32768) {                            // W1: n 256, k 128
            int n = i >> 7, k = i & 127;
            float w = W1[k * C1 + n];
            __nv_bfloat16 h = __float2bfloat16(w);
            __nv_bfloat16 l = __float2bfloat16(w - __bfloat162float(h));
            g_W1i_hi[n * 136 + k] = __bfloat16_as_ushort(h);
            g_W1i_lo[n * 136 + k] = __bfloat16_as_ushort(l);
        } else {                                    // W2: n 128, k 256, k-halved
            int j = i - 32768;
            int n = j >> 8, k = j & 255;
            float w = W2[k * C0 + n];
            __nv_bfloat16 h = __float2bfloat16(w);
            __nv_bfloat16 l = __float2bfloat16(w - __bfloat162float(h));
            int kh = k >> 7, kk = k & 127;
            g_W2i_hi[kh * 128 * 136 + n * 136 + kk] = __bfloat16_as_ushort(h);
            g_W2i_lo[kh * 128 * 136 + n * 136 + kk] = __bfloat16_as_ushort(l);
        }
        return;
    }

    __shared__ float emb[32][EMBD];
    __shared__ float ff[32][4];

    if (blk < 640) {                                // ---- px ----
        int q0 = (blk - 512) * 32;
        for (int idx = t; idx < 32 * 48; idx += 128) {
            int pt = idx / 48, rem = idx % 48;
            int c = rem >> 4, i = rem & 15;
            float coord = latent[(q0 + pt) * 3 + c];
            float sv, cv; __sincosf(coord * c_freq[i], &sv, &cv);
            emb[pt][c * 32 + i] = sv;
            emb[pt][c * 32 + 16 + i] = cv;
        }
        __syncthreads();
        float acc[32];
        float bias = b0[t];
        #pragma unroll
        for (int p = 0; p < 32; p++) acc[p] = bias;
        #pragma unroll 2
        for (int e = 0; e < EMBD; e += 4) {
            float w0 = W0[(96 + e) * C0 + t];
            float w1 = W0[(97 + e) * C0 + t];
            float w2 = W0[(98 + e) * C0 + t];
            float w3 = W0[(99 + e) * C0 + t];
            #pragma unroll
            for (int p = 0; p < 32; p++) {
                float4 ev = *(const float4*)&emb[p][e];
                acc[p] += ev.x * w0 + ev.y * w1 + ev.z * w2 + ev.w * w3;
            }
        }
        float* dst = g_Px + (size_t)q0 * C0 + t;
        #pragma unroll
        for (int p = 0; p < 32; p++) dst[p * C0] = acc[p];
        return;
    }

    // ---- a ----
    int ablk = blk - 640;
    int b = ablk >> 10;
    int j0 = (ablk & 1023) * 32;
    for (int idx = t; idx < 32 * 48; idx += 128) {
        int pt = idx / 48, rem = idx % 48;
        int c = rem >> 4, i = rem & 15;
        float coord = gc[((size_t)(b * NPTS) + j0 + pt) * 3 + c];
        float sv, cv; __sincosf(coord * c_freq[i], &sv, &cv);
        emb[pt][c * 32 + i] = sv;
        emb[pt][c * 32 + 16 + i] = cv;
    }
    {
        int pt = t >> 2, c = t & 3;
        int j = j0 + pt;
        int d = j & 31, w = (j >> 5) & 31, h = j >> 10;
        ff[pt][c] = x[(size_t)(b * 4 + c) * NPTS + (size_t)d * 1024 + h * 32 + w];
    }
    __syncthreads();
    float acc[32];
    #pragma unroll
    for (int p = 0; p < 32; p++) acc[p] = 0.0f;
    #pragma unroll 2
    for (int e = 0; e < EMBD; e += 4) {
        float w0 = W0[(e + 0) * C0 + t];
        float w1 = W0[(e + 1) * C0 + t];
        float w2 = W0[(e + 2) * C0 + t];
        float w3 = W0[(e + 3) * C0 + t];
        #pragma unroll
        for (int p = 0; p < 32; p++) {
            float4 ev = *(const float4*)&emb[p][e];
            acc[p] += ev.x * w0 + ev.y * w1 + ev.z * w2 + ev.w * w3;
        }
    }
    #pragma unroll
    for (int e = 0; e < 4; e++) {
        float w = W0[(192 + e) * C0 + t];
        #pragma unroll
        for (int p = 0; p < 32; p++) acc[p] += ff[p][e] * w;
    }
    float* dst = g_A + ((size_t)(b * NPTS + j0)) * C0 + t;
    #pragma unroll
    for (int p = 0; p < 32; p++) dst[p * C0] = acc[p];
}

// ---------------------------------------------------------------------------
// main6 — 2 queries/block (M=64), 8 warps (2m x 4n), 2 CTAs/SM,
// single-W-image sequential staging, fused 3-pass bf16.
// ---------------------------------------------------------------------------
__global__ void __launch_bounds__(256, 2) main6_kernel(const int* __restrict__ nbr_idx,
                                                       const unsigned int* __restrict__ nbr_mask,
                                                       const float* __restrict__ b1,
                                                       const float* __restrict__ b2,
                                                       const float* __restrict__ W3,
                                                       const float* __restrict__ b3,
                                                       float* __restrict__ out) {
    extern __shared__ char dsm_raw[];
    __shared__ int   sidx[64];
    __shared__ float smsk[64];
    __shared__ float s_hs[2][128];
    __shared__ float s_nv[2];

    u32 raw = smem_u32(dsm_raw);
    u32 base = (raw + 127u) & ~127u;
    char* dsm = dsm_raw + (base - raw);

    int t    = threadIdx.x;
    int w    = t >> 5;
    int lane = t & 31;
    int wm   = w & 1;           // rows 32*wm .. +31
    int wn   = w >> 1;          // 0..3
    int blk  = blockIdx.x;
    int b    = blk >> 11;
    int q0   = (blk & 2047) << 1;

    // ldmatrix lane offsets
    u32 aL1 = (u32)(lane & 15) * PB1 + (u32)(lane >> 4) * 16;
    u32 aL2 = (u32)(lane & 15) * PB2 + (u32)(lane >> 4) * 16;
    u32 bL1 = ((u32)(lane & 7) + (u32)((lane >> 4) << 3)) * PB1 + (u32)(((lane >> 3) & 1) << 4);

    // ---- neighbor meta + stage W1hi ----
    if (t < 64) {
        int ib = (b * NQ + q0) * KNBR + t;
        sidx[t] = nbr_idx[ib];
        smsk[t] = (nbr_mask[ib] != 0u) ? 1.0f : 0.0f;   // 4-byte bool encoding
    }
    {
        const int4* s1 = (const int4*)g_W1i_hi;
        int4* d1 = (int4*)(dsm + OFF_W1);
        for (int i = t; i < 4352; i += 256) d1[i] = s1[i];
    }
    __syncthreads();

    // ---- phase A: gather + gelu + split into A1 (64 rows) ----
    {
        const float* Px0 = g_Px + (size_t)q0 * C0;
        #pragma unroll 4
        for (int idx = t; idx < 64 * 64; idx += 256) {
            int r = idx >> 6, cp = idx & 63;
            float2 av = *(const float2*)(g_A + ((size_t)(b * NPTS + sidx[r])) * C0 + 2 * cp);
            float2 pv = *(const float2*)(Px0 + (size_t)(r >> 5) * C0 + 2 * cp);
            float v0 = gelu_fast(av.x + pv.x);
            float v1 = gelu_fast(av.y + pv.y);
            u32 hi, lo; split_pack(v0, v1, hi, lo);
            u32 off = (u32)r * PB1 + (u32)cp * 4;
            *(u32*)(dsm + OFF_A1HI + off) = hi;
            *(u32*)(dsm + OFF_A1LO + off) = lo;
        }
    }
    __syncthreads();

    // ---- layer 1: warp tile 32x64; passes (Ahi+Alo)xWhi then AhixWlo ----
    float acc1[2][8][4] = {};
    u32 aHi1 = base + OFF_A1HI + (u32)(wm * 32) * PB1 + aL1;
    u32 aLo1 = base + OFF_A1LO + (u32)(wm * 32) * PB1 + aL1;
    u32 wB1  = base + OFF_W1 + (u32)(wn * 64) * PB1 + bL1;
    for (int ks = 0; ks < 8; ks++) {
        u32 koff = ks * 32;
        u32 ah[2][4], al[2][4];
        ldsm_x4(ah[0], aHi1 + koff);
        ldsm_x4(ah[1], aHi1 + 16 * PB1 + koff);
        ldsm_x4(al[0], aLo1 + koff);
        ldsm_x4(al[1], aLo1 + 16 * PB1 + koff);
        #pragma unroll
        for (int nj = 0; nj < 4; nj++) {
            u32 bh[4];
            ldsm_x4(bh, wB1 + (u32)(nj * 16) * PB1 + koff);
            #pragma unroll
            for (int mi = 0; mi < 2; mi++) {
                mma16816(acc1[mi][2 * nj],     ah[mi], bh);
                mma16816(acc1[mi][2 * nj + 1], ah[mi], bh + 2);
                mma16816(acc1[mi][2 * nj],     al[mi], bh);
                mma16816(acc1[mi][2 * nj + 1], al[mi], bh + 2);
            }
        }
    }
    __syncthreads();
    {   // restage W1lo into same buffer
        const int4* s1 = (const int4*)g_W1i_lo;
        int4* d1 = (int4*)(dsm + OFF_W1);
        for (int i = t; i < 4352; i += 256) d1[i] = s1[i];
    }
    __syncthreads();
    for (int ks = 0; ks < 8; ks++) {
        u32 koff = ks * 32;
        u32 ah[2][4];
        ldsm_x4(ah[0], aHi1 + koff);
        ldsm_x4(ah[1], aHi1 + 16 * PB1 + koff);
        #pragma unroll
        for (int nj = 0; nj < 4; nj++) {
            u32 bl[4];
            ldsm_x4(bl, wB1 + (u32)(nj * 16) * PB1 + koff);
            #pragma unroll
            for (int mi = 0; mi < 2; mi++) {
                mma16816(acc1[mi][2 * nj],     ah[mi], bl);
                mma16816(acc1[mi][2 * nj + 1], ah[mi], bl + 2);
            }
        }
    }
    __syncthreads();   // A1/W1 reads done; regions reused below

    // ---- epilogue 1: h1 = gelu(C1 + b1) -> A2 hi/lo ----
    {
        #pragma unroll
        for (int mi = 0; mi < 2; mi++)
            #pragma unroll
            for (int ni = 0; ni < 8; ni++) {
                const float* cc = acc1[mi][ni];
                int col = wn * 64 + ni * 8 + (lane & 3) * 2;
                int r0  = wm * 32 + mi * 16 + (lane >> 2);
                float2 bv = *(const float2*)(b1 + col);
                u32 hi, lo;
                split_pack(gelu_fast(cc[0] + bv.x), gelu_fast(cc[1] + bv.y), hi, lo);
                u32 off = (u32)r0 * PB2 + (u32)col * 2;
                *(u32*)(dsm + OFF_A2HI + off) = hi;
                *(u32*)(dsm + OFF_A2LO + off) = lo;
                split_pack(gelu_fast(cc[2] + bv.x), gelu_fast(cc[3] + bv.y), hi, lo);
                off = (u32)(r0 + 8) * PB2 + (u32)col * 2;
                *(u32*)(dsm + OFF_A2HI + off) = hi;
                *(u32*)(dsm + OFF_A2LO + off) = lo;
            }
    }

    // ---- layer 2: warp tile 32x32, K=256 via 2 k-halves, W staged hi/lo ----
    float acc2[2][4][4] = {};
    u32 aHi2 = base + OFF_A2HI + (u32)(wm * 32) * PB2 + aL2;
    u32 aLo2 = base + OFF_A2LO + (u32)(wm * 32) * PB2 + aL2;
    u32 wB2  = base + OFF_W2 + (u32)(wn * 32) * PB1 + bL1;
    #pragma unroll 1
    for (int kh = 0; kh < 2; kh++) {
        __syncthreads();    // A2 visible (kh=0) / prior W2 readers done (kh=1)
        {
            const int4* s1 = (const int4*)(g_W2i_hi + kh * 17408);
            int4* d1 = (int4*)(dsm + OFF_W2);
            for (int i = t; i < 2176; i += 256) d1[i] = s1[i];
        }
        __syncthreads();
        u32 akh = (u32)kh * 256;
        for (int ks = 0; ks < 8; ks++) {
            u32 koff = ks * 32;
            u32 ah[2][4], al[2][4];
            ldsm_x4(ah[0], aHi2 + akh + koff);
            ldsm_x4(ah[1], aHi2 + akh + 16 * PB2 + koff);
            ldsm_x4(al[0], aLo2 + akh + koff);
            ldsm_x4(al[1], aLo2 + akh + 16 * PB2 + koff);
            #pragma unroll
            for (int nj = 0; nj < 2; nj++) {
                u32 bh[4];
                ldsm_x4(bh, wB2 + (u32)(nj * 16) * PB1 + koff);
                #pragma unroll
                for (int mi = 0; mi < 2; mi++) {
                    mma16816(acc2[mi][2 * nj],     ah[mi], bh);
                    mma16816(acc2[mi][2 * nj + 1], ah[mi], bh + 2);
                    mma16816(acc2[mi][2 * nj],     al[mi], bh);
                    mma16816(acc2[mi][2 * nj + 1], al[mi], bh + 2);
                }
            }
        }
        __syncthreads();
        {
            const int4* s1 = (const int4*)(g_W2i_lo + kh * 17408);
            int4* d1 = (int4*)(dsm + OFF_W2);
            for (int i = t; i < 2176; i += 256) d1[i] = s1[i];
        }
        __syncthreads();
        for (int ks = 0; ks < 8; ks++) {
            u32 koff = ks * 32;
            u32 ah[2][4];
            ldsm_x4(ah[0], aHi2 + akh + koff);
            ldsm_x4(ah[1], aHi2 + akh + 16 * PB2 + koff);
            #pragma unroll
            for (int nj = 0; nj < 2; nj++) {
                u32 bl[4];
                ldsm_x4(bl, wB2 + (u32)(nj * 16) * PB1 + koff);
                #pragma unroll
                for (int mi = 0; mi < 2; mi++) {
                    mma16816(acc2[mi][2 * nj],     ah[mi], bl);
                    mma16816(acc2[mi][2 * nj + 1], ah[mi], bl + 2);
                }
            }
        }
    }
    __syncthreads();   // A2/W2 reads done

    // ---- epilogue 2: h2 = gelu(C2 + b2) -> floats at OFF_H2 ----
    {
        float* h2 = (float*)(dsm + OFF_H2);
        #pragma unroll
        for (int mi = 0; mi < 2; mi++)
            #pragma unroll
            for (int ni = 0; ni < 4; ni++) {
                const float* cc = acc2[mi][ni];
                int col = wn * 32 + ni * 8 + (lane & 3) * 2;
                int r0  = wm * 32 + mi * 16 + (lane >> 2);
                float2 bv = *(const float2*)(b2 + col);
                *(float2*)(h2 + r0 * PH2 + col) =
                    make_float2(gelu_fast(cc[0] + bv.x), gelu_fast(cc[1] + bv.y));
                *(float2*)(h2 + (r0 + 8) * PH2 + col) =
                    make_float2(gelu_fast(cc[2] + bv.x), gelu_fast(cc[3] + bv.y));
            }
    }
    __syncthreads();

    // ---- phase D: masked row-sums (256 threads: qg = t>>7, c = t&127) ----
    {
        const float* h2 = (const float*)(dsm + OFF_H2);
        int c = t & 127, qg = t >> 7;
        float s = 0.0f;
        #pragma unroll
        for (int k = 0; k < 32; k++) s += smsk[qg * 32 + k] * h2[(qg * 32 + k) * PH2 + c];
        s_hs[qg][c] = s;
        if (t < 2) {
            float nv = 0.0f;
            #pragma unroll
            for (int k = 0; k < 32; k++) nv += smsk[t * 32 + k];
            s_nv[t] = nv;
        }
    }
    __syncthreads();

    // ---- phase E: out = hs @ W3 + nv*b3 ----
    {
        int c = t & 127, qg = t >> 7;
        float acc = s_nv[qg] * b3[c];
        #pragma unroll 4
        for (int j = 0; j < 128; j++) acc += s_hs[qg][j] * W3[j * C0 + c];
        int q = q0 + qg;
        int dl = q & 15, wl = (q >> 4) & 15, hl = q >> 8;
        out[((((size_t)b * 128 + c) * 16 + dl) * 16 + hl) * 16 + wl] = acc;
    }
}

extern "C" void kernel_launch(void* const* d_in, const int* in_sizes, int n_in,
                              void* d_out, int out_size) {
    const float* x        = (const float*)d_in[0];
    const float* gc       = (const float*)d_in[1];
    const float* latent   = (const float*)d_in[2];
    const int*   nbr_idx  = (const int*)d_in[3];
    const unsigned int* nbr_mask = (const unsigned int*)d_in[4];
    const float* W0 = (const float*)d_in[5];
    const float* b0 = (const float*)d_in[6];
    const float* W1 = (const float*)d_in[7];
    const float* b1 = (const float*)d_in[8];
    const float* W2 = (const float*)d_in[9];
    const float* b2 = (const float*)d_in[10];
    const float* W3 = (const float*)d_in[11];
    const float* b3 = (const float*)d_in[12];
    float* out = (float*)d_out;

    cudaFuncSetAttribute(main6_kernel, cudaFuncAttributeMaxDynamicSharedMemorySize,
                         DSM_BYTES);

    prep_kernel<<<2688, 128>>>(x, gc, latent, W0, b0, W1, W2);
    main6_kernel<<<BATCH * NQ / 2, 256, DSM_BYTES>>>(nbr_idx, nbr_mask,
                                                     b1, b2, W3, b3, out);
}

// round 14
// speedup vs baseline: 1.1738x; 1.1738x over previous
#include <cuda_runtime.h>
#include <cuda_fp16.h>
#include <math.h>

#define NPTS  32768
#define NQ    4096
#define BATCH 2
#define KNBR  32
#define EMBD  96
#define C0    128
#define C1    256

typedef unsigned int u32;
typedef unsigned short u16;

// ---------------- global scratch (no allocation allowed) ----------------
__device__ float g_A[BATCH * NPTS * C0];
__device__ float g_Px[NQ * C0];             // batch-independent (bbox == [0,1]^3)
// fp16 weight images (single, round-to-nearest), B-operand form [n][k], pitch k+8
__device__ __align__(16) u16 g_W1i[256 * 136];    // [n=256][k=128]
__device__ __align__(16) u16 g_W2i[128 * 264];    // [n=128][k=256]

__constant__ float c_freq[16] = {
    1.0f, 0.562341325190349f, 0.316227766016838f, 0.177827941003892f,
    0.1f, 0.0562341325190349f, 0.0316227766016838f, 0.0177827941003892f,
    0.01f, 0.00562341325190349f, 0.00316227766016838f, 0.00177827941003892f,
    0.001f, 0.000562341325190349f, 0.000316227766016838f, 0.000177827941003892f };

// pitches (bytes)
#define PB1 272     // rows of A1/W1: 136 halves
#define PB2 528     // rows of A2/W2: 264 halves
#define PH2 132     // h2 floats pitch

// smem regions (bytes from aligned base); peak 202752
#define OFF_A1HI 0            // 128*272 = 34816
#define OFF_A1LO 34816        // end 69632
#define OFF_W1   69632        // 256*272 = 69632, end 139264
#define OFF_A2HI 0            // 128*528 = 67584
#define OFF_A2LO 67584        // end 135168
#define OFF_W2   135168       // 128*528 = 67584, end 202752
#define OFF_H2   0            // 128*132*4 = 67584
#define DSM_BYTES (202752 + 128)

static __device__ __forceinline__ u32 smem_u32(const void* p) {
    u32 a; asm("{ .reg .u64 t; cvta.to.shared.u64 t, %1; cvt.u32.u64 %0, t; }" : "=r"(a) : "l"(p));
    return a;
}
__device__ __forceinline__ void ldsm_x4(u32* r, u32 addr) {
    asm volatile("ldmatrix.sync.aligned.m8n8.x4.shared.b16 {%0,%1,%2,%3}, [%4];"
        : "=r"(r[0]), "=r"(r[1]), "=r"(r[2]), "=r"(r[3]) : "r"(addr));
}
__device__ __forceinline__ void mma_h(float* c, const u32* a, const u32* b) {
    asm volatile("mma.sync.aligned.m16n8k16.row.col.f32.f16.f16.f32 "
        "{%0,%1,%2,%3}, {%4,%5,%6,%7}, {%8,%9}, {%0,%1,%2,%3};"
        : "+f"(c[0]), "+f"(c[1]), "+f"(c[2]), "+f"(c[3])
        : "r"(a[0]), "r"(a[1]), "r"(a[2]), "r"(a[3]), "r"(b[0]), "r"(b[1]));
}
__device__ __forceinline__ float gelu_fast(float x) {
    float z = 1.5957691216057308f * (x + 0.044715f * x * x * x);
    return x * __frcp_rn(1.0f + __expf(-z));
}
__device__ __forceinline__ void split_pack_h(float v0, float v1, u32& hi, u32& lo) {
    __half h0 = __float2half_rn(v0), h1 = __float2half_rn(v1);
    float r0 = v0 - __half2float(h0), r1 = v1 - __half2float(h1);
    __half l0 = __float2half_rn(r0), l1 = __float2half_rn(r1);
    hi = (u32)__half_as_ushort(h0) | ((u32)__half_as_ushort(h1) << 16);
    lo = (u32)__half_as_ushort(l0) | ((u32)__half_as_ushort(l1) << 16);
}

// ---------------------------------------------------------------------------
// prep: blocks [0,512) wpack | [512,640) px | [640,2688) a
// ---------------------------------------------------------------------------
__global__ void __launch_bounds__(128) prep_kernel(const float* __restrict__ x,
                                                   const float* __restrict__ gc,
                                                   const float* __restrict__ latent,
                                                   const float* __restrict__ W0,
                                                   const float* __restrict__ b0,
                                                   const float* __restrict__ W1,
                                                   const float* __restrict__ W2) {
    int blk = blockIdx.x;
    int t = threadIdx.x;

    if (blk < 512) {                                // ---- wpack (fp16 single) ----
        int i = blk * 128 + t;
        if (i < 32768) {                            // W1: n 256, k 128
            int n = i >> 7, k = i & 127;
            g_W1i[n * 136 + k] = __half_as_ushort(__float2half_rn(W1[k * C1 + n]));
        } else {                                    // W2: n 128, k 256
            int j = i - 32768;
            int n = j >> 8, k = j & 255;
            g_W2i[n * 264 + k] = __half_as_ushort(__float2half_rn(W2[k * C0 + n]));
        }
        return;
    }

    __shared__ float emb[32][EMBD];
    __shared__ float ff[32][4];

    if (blk < 640) {                                // ---- px ----
        int q0 = (blk - 512) * 32;
        for (int idx = t; idx < 32 * 48; idx += 128) {
            int pt = idx / 48, rem = idx % 48;
            int c = rem >> 4, i = rem & 15;
            float coord = latent[(q0 + pt) * 3 + c];
            float sv, cv; __sincosf(coord * c_freq[i], &sv, &cv);
            emb[pt][c * 32 + i] = sv;
            emb[pt][c * 32 + 16 + i] = cv;
        }
        __syncthreads();
        float acc[32];
        float bias = b0[t];
        #pragma unroll
        for (int p = 0; p < 32; p++) acc[p] = bias;
        #pragma unroll 2
        for (int e = 0; e < EMBD; e += 4) {
            float w0 = W0[(96 + e) * C0 + t];
            float w1 = W0[(97 + e) * C0 + t];
            float w2 = W0[(98 + e) * C0 + t];
            float w3 = W0[(99 + e) * C0 + t];
            #pragma unroll
            for (int p = 0; p < 32; p++) {
                float4 ev = *(const float4*)&emb[p][e];
                acc[p] += ev.x * w0 + ev.y * w1 + ev.z * w2 + ev.w * w3;
            }
        }
        float* dst = g_Px + (size_t)q0 * C0 + t;
        #pragma unroll
        for (int p = 0; p < 32; p++) dst[p * C0] = acc[p];
        return;
    }

    // ---- a ----
    int ablk = blk - 640;
    int b = ablk >> 10;
    int j0 = (ablk & 1023) * 32;
    for (int idx = t; idx < 32 * 48; idx += 128) {
        int pt = idx / 48, rem = idx % 48;
        int c = rem >> 4, i = rem & 15;
        float coord = gc[((size_t)(b * NPTS) + j0 + pt) * 3 + c];
        float sv, cv; __sincosf(coord * c_freq[i], &sv, &cv);
        emb[pt][c * 32 + i] = sv;
        emb[pt][c * 32 + 16 + i] = cv;
    }
    {
        int pt = t >> 2, c = t & 3;
        int j = j0 + pt;
        int d = j & 31, w = (j >> 5) & 31, h = j >> 10;
        ff[pt][c] = x[(size_t)(b * 4 + c) * NPTS + (size_t)d * 1024 + h * 32 + w];
    }
    __syncthreads();
    float acc[32];
    #pragma unroll
    for (int p = 0; p < 32; p++) acc[p] = 0.0f;
    #pragma unroll 2
    for (int e = 0; e < EMBD; e += 4) {
        float w0 = W0[(e + 0) * C0 + t];
        float w1 = W0[(e + 1) * C0 + t];
        float w2 = W0[(e + 2) * C0 + t];
        float w3 = W0[(e + 3) * C0 + t];
        #pragma unroll
        for (int p = 0; p < 32; p++) {
            float4 ev = *(const float4*)&emb[p][e];
            acc[p] += ev.x * w0 + ev.y * w1 + ev.z * w2 + ev.w * w3;
        }
    }
    #pragma unroll
    for (int e = 0; e < 4; e++) {
        float w = W0[(192 + e) * C0 + t];
        #pragma unroll
        for (int p = 0; p < 32; p++) acc[p] += ff[p][e] * w;
    }
    float* dst = g_A + ((size_t)(b * NPTS + j0)) * C0 + t;
    #pragma unroll
    for (int p = 0; p < 32; p++) dst[p * C0] = acc[p];
}

// ---------------------------------------------------------------------------
// main7 — 4 queries/block (M=128), 16 warps (4m x 4n), fp16 2-pass split.
// ---------------------------------------------------------------------------
__global__ void __launch_bounds__(512, 1) main7_kernel(const int* __restrict__ nbr_idx,
                                                       const unsigned int* __restrict__ nbr_mask,
                                                       const float* __restrict__ b1,
                                                       const float* __restrict__ b2,
                                                       const float* __restrict__ W3,
                                                       const float* __restrict__ b3,
                                                       float* __restrict__ out) {
    extern __shared__ char dsm_raw[];
    __shared__ int   sidx[128];
    __shared__ float smsk[128];
    __shared__ float s_hs[4][128];
    __shared__ float s_nv[4];

    u32 raw = smem_u32(dsm_raw);
    u32 base = (raw + 127u) & ~127u;
    char* dsm = dsm_raw + (base - raw);

    int t    = threadIdx.x;
    int w    = t >> 5;
    int lane = t & 31;
    int wm   = w & 3;           // rows 32*wm .. +31
    int wn   = w >> 2;          // 0..3
    int blk  = blockIdx.x;
    int b    = blk >> 10;
    int q0   = (blk & 1023) << 2;

    // ldmatrix lane offsets
    u32 aL1 = (u32)(lane & 15) * PB1 + (u32)(lane >> 4) * 16;
    u32 aL2 = (u32)(lane & 15) * PB2 + (u32)(lane >> 4) * 16;
    u32 bL1 = ((u32)(lane & 7) + (u32)((lane >> 4) << 3)) * PB1 + (u32)(((lane >> 3) & 1) << 4);
    u32 bL2 = ((u32)(lane & 7) + (u32)((lane >> 4) << 3)) * PB2 + (u32)(((lane >> 3) & 1) << 4);

    // ---- neighbor meta + stage W1 image ----
    if (t < 128) {
        int ib = (b * NQ + q0) * KNBR + t;
        sidx[t] = nbr_idx[ib];
        smsk[t] = (nbr_mask[ib] != 0u) ? 1.0f : 0.0f;   // 4-byte bool encoding
    }
    {
        const int4* s1 = (const int4*)g_W1i;
        int4* d1 = (int4*)(dsm + OFF_W1);
        for (int i = t; i < 4352; i += 512) d1[i] = s1[i];
    }
    __syncthreads();

    // ---- phase A: gather + gelu + fp16 split into A1 ----
    {
        const float* Px0 = g_Px + (size_t)q0 * C0;
        #pragma unroll 4
        for (int idx = t; idx < 128 * 64; idx += 512) {
            int r = idx >> 6, cp = idx & 63;
            float2 av = *(const float2*)(g_A + ((size_t)(b * NPTS + sidx[r])) * C0 + 2 * cp);
            float2 pv = *(const float2*)(Px0 + (size_t)(r >> 5) * C0 + 2 * cp);
            float v0 = gelu_fast(av.x + pv.x);
            float v1 = gelu_fast(av.y + pv.y);
            u32 hi, lo; split_pack_h(v0, v1, hi, lo);
            u32 off = (u32)r * PB1 + (u32)cp * 4;
            *(u32*)(dsm + OFF_A1HI + off) = hi;
            *(u32*)(dsm + OFF_A1LO + off) = lo;
        }
    }
    __syncthreads();

    // ---- layer 1: warp tile 32x64, 2-pass (Ahi, Alo) x W ----
    float acc1[2][8][4] = {};
    {
        u32 aHi = base + OFF_A1HI + (u32)(wm * 32) * PB1 + aL1;
        u32 aLo = base + OFF_A1LO + (u32)(wm * 32) * PB1 + aL1;
        u32 wB  = base + OFF_W1 + (u32)(wn * 64) * PB1 + bL1;
        for (int ks = 0; ks < 8; ks++) {
            u32 koff = ks * 32;
            u32 ah[2][4], al[2][4], bb[4][4];
            ldsm_x4(ah[0], aHi + koff);
            ldsm_x4(ah[1], aHi + 16 * PB1 + koff);
            ldsm_x4(al[0], aLo + koff);
            ldsm_x4(al[1], aLo + 16 * PB1 + koff);
            #pragma unroll
            for (int nj = 0; nj < 4; nj++)
                ldsm_x4(bb[nj], wB + (u32)(nj * 16) * PB1 + koff);
            #pragma unroll
            for (int nj = 0; nj < 4; nj++)
                #pragma unroll
                for (int mi = 0; mi < 2; mi++) {
                    mma_h(acc1[mi][2 * nj],     ah[mi], bb[nj]);
                    mma_h(acc1[mi][2 * nj + 1], ah[mi], bb[nj] + 2);
                }
            #pragma unroll
            for (int nj = 0; nj < 4; nj++)
                #pragma unroll
                for (int mi = 0; mi < 2; mi++) {
                    mma_h(acc1[mi][2 * nj],     al[mi], bb[nj]);
                    mma_h(acc1[mi][2 * nj + 1], al[mi], bb[nj] + 2);
                }
        }
    }
    __syncthreads();   // A1/W1 reads done; regions reused below

    // ---- epilogue 1: h1 = gelu(C1 + b1) -> A2 hi/lo; stage W2 image ----
    {
        #pragma unroll
        for (int mi = 0; mi < 2; mi++)
            #pragma unroll
            for (int ni = 0; ni < 8; ni++) {
                const float* cc = acc1[mi][ni];
                int col = wn * 64 + ni * 8 + (lane & 3) * 2;
                int r0  = wm * 32 + mi * 16 + (lane >> 2);
                float2 bv = *(const float2*)(b1 + col);
                u32 hi, lo;
                split_pack_h(gelu_fast(cc[0] + bv.x), gelu_fast(cc[1] + bv.y), hi, lo);
                u32 off = (u32)r0 * PB2 + (u32)col * 2;
                *(u32*)(dsm + OFF_A2HI + off) = hi;
                *(u32*)(dsm + OFF_A2LO + off) = lo;
                split_pack_h(gelu_fast(cc[2] + bv.x), gelu_fast(cc[3] + bv.y), hi, lo);
                off = (u32)(r0 + 8) * PB2 + (u32)col * 2;
                *(u32*)(dsm + OFF_A2HI + off) = hi;
                *(u32*)(dsm + OFF_A2LO + off) = lo;
            }
        const int4* s1 = (const int4*)g_W2i;
        int4* d1 = (int4*)(dsm + OFF_W2);
        for (int i = t; i < 4224; i += 512) d1[i] = s1[i];
    }
    __syncthreads();

    // ---- layer 2: warp tile 32x32, K=256, 2-pass ----
    float acc2[2][4][4] = {};
    {
        u32 aHi = base + OFF_A2HI + (u32)(wm * 32) * PB2 + aL2;
        u32 aLo = base + OFF_A2LO + (u32)(wm * 32) * PB2 + aL2;
        u32 wB  = base + OFF_W2 + (u32)(wn * 32) * PB2 + bL2;
        for (int ks = 0; ks < 16; ks++) {
            u32 koff = ks * 32;
            u32 ah[2][4], al[2][4], bb[2][4];
            ldsm_x4(ah[0], aHi + koff);
            ldsm_x4(ah[1], aHi + 16 * PB2 + koff);
            ldsm_x4(al[0], aLo + koff);
            ldsm_x4(al[1], aLo + 16 * PB2 + koff);
            #pragma unroll
            for (int nj = 0; nj < 2; nj++)
                ldsm_x4(bb[nj], wB + (u32)(nj * 16) * PB2 + koff);
            #pragma unroll
            for (int nj = 0; nj < 2; nj++)
                #pragma unroll
                for (int mi = 0; mi < 2; mi++) {
                    mma_h(acc2[mi][2 * nj],     ah[mi], bb[nj]);
                    mma_h(acc2[mi][2 * nj + 1], ah[mi], bb[nj] + 2);
                }
            #pragma unroll
            for (int nj = 0; nj < 2; nj++)
                #pragma unroll
                for (int mi = 0; mi < 2; mi++) {
                    mma_h(acc2[mi][2 * nj],     al[mi], bb[nj]);
                    mma_h(acc2[mi][2 * nj + 1], al[mi], bb[nj] + 2);
                }
        }
    }
    __syncthreads();   // A2/W2 reads done

    // ---- epilogue 2: h2 = gelu(C2 + b2) -> floats at OFF_H2 ----
    {
        float* h2 = (float*)(dsm + OFF_H2);
        #pragma unroll
        for (int mi = 0; mi < 2; mi++)
            #pragma unroll
            for (int ni = 0; ni < 4; ni++) {
                const float* cc = acc2[mi][ni];
                int col = wn * 32 + ni * 8 + (lane & 3) * 2;
                int r0  = wm * 32 + mi * 16 + (lane >> 2);
                float2 bv = *(const float2*)(b2 + col);
                *(float2*)(h2 + r0 * PH2 + col) =
                    make_float2(gelu_fast(cc[0] + bv.x), gelu_fast(cc[1] + bv.y));
                *(float2*)(h2 + (r0 + 8) * PH2 + col) =
                    make_float2(gelu_fast(cc[2] + bv.x), gelu_fast(cc[3] + bv.y));
            }
    }
    __syncthreads();

    // ---- phase D: masked row-sums (512 threads: qg = t>>7, c = t&127) ----
    {
        const float* h2 = (const float*)(dsm + OFF_H2);
        int c = t & 127, qg = t >> 7;
        float s = 0.0f;
        #pragma unroll
        for (int k = 0; k < 32; k++) s += smsk[qg * 32 + k] * h2[(qg * 32 + k) * PH2 + c];
        s_hs[qg][c] = s;
        if (t < 4) {
            float nv = 0.0f;
            #pragma unroll
            for (int k = 0; k < 32; k++) nv += smsk[t * 32 + k];
            s_nv[t] = nv;
        }
    }
    __syncthreads();

    // ---- phase E: out = hs @ W3 + nv*b3 ----
    {
        int c = t & 127, qg = t >> 7;
        float acc = s_nv[qg] * b3[c];
        #pragma unroll 4
        for (int j = 0; j < 128; j++) acc += s_hs[qg][j] * W3[j * C0 + c];
        int q = q0 + qg;
        int dl = q & 15, wl = (q >> 4) & 15, hl = q >> 8;
        out[((((size_t)b * 128 + c) * 16 + dl) * 16 + hl) * 16 + wl] = acc;
    }
}

extern "C" void kernel_launch(void* const* d_in, const int* in_sizes, int n_in,
                              void* d_out, int out_size) {
    const float* x        = (const float*)d_in[0];
    const float* gc       = (const float*)d_in[1];
    const float* latent   = (const float*)d_in[2];
    const int*   nbr_idx  = (const int*)d_in[3];
    const unsigned int* nbr_mask = (const unsigned int*)d_in[4];
    const float* W0 = (const float*)d_in[5];
    const float* b0 = (const float*)d_in[6];
    const float* W1 = (const float*)d_in[7];
    const float* b1 = (const float*)d_in[8];
    const float* W2 = (const float*)d_in[9];
    const float* b2 = (const float*)d_in[10];
    const float* W3 = (const float*)d_in[11];
    const float* b3 = (const float*)d_in[12];
    float* out = (float*)d_out;

    cudaFuncSetAttribute(main7_kernel, cudaFuncAttributeMaxDynamicSharedMemorySize,
                         DSM_BYTES);

    prep_kernel<<<2688, 128>>>(x, gc, latent, W0, b0, W1, W2);
    main7_kernel<<<BATCH * NQ / 4, 512, DSM_BYTES>>>(nbr_idx, nbr_mask,
                                                     b1, b2, W3, b3, out);
}

// round 15
// speedup vs baseline: 1.4440x; 1.2302x over previous
#include <cuda_runtime.h>
#include <cuda_fp16.h>
#include <math.h>

#define NPTS  32768
#define NQ    4096
#define BATCH 2
#define KNBR  32
#define EMBD  96
#define C0    128
#define C1    256

typedef unsigned int u32;
typedef unsigned short u16;

// ---------------- global scratch (no allocation allowed) ----------------
__device__ float g_A[BATCH * NPTS * C0];
__device__ float g_Px[NQ * C0];             // batch-independent (bbox == [0,1]^3)
// fp16 weight images (round-to-nearest), B-operand form [n][k], pitch k+8
__device__ __align__(16) u16 g_W1i[256 * 136];        // [n=256][k=128]
__device__ __align__(16) u16 g_W2i[2 * 128 * 136];    // [khalf][n=128][k'=128]

__constant__ float c_freq[16] = {
    1.0f, 0.562341325190349f, 0.316227766016838f, 0.177827941003892f,
    0.1f, 0.0562341325190349f, 0.0316227766016838f, 0.0177827941003892f,
    0.01f, 0.00562341325190349f, 0.00316227766016838f, 0.00177827941003892f,
    0.001f, 0.000562341325190349f, 0.000316227766016838f, 0.000177827941003892f };

// pitches (bytes)
#define PB1 272     // rows of A1/W1/W2half: 136 halves
#define PB2 528     // rows of A2: 264 halves
#define PH2 132     // h2 floats pitch

// smem regions (bytes from aligned base); peak 104448 -> 2 CTAs/SM
#define OFF_A1HI 0            // 64*272 = 17408
#define OFF_A1LO 17408        // end 34816
#define OFF_W1   34816        // 256*272 = 69632, end 104448
#define OFF_A2HI 0            // 64*528 = 33792
#define OFF_A2LO 33792        // end 67584
#define OFF_W2   67584        // 128*272 = 34816, end 102400
#define OFF_H2   0            // 64*132*4 = 33792
#define DSM_BYTES (104448 + 128)

static __device__ __forceinline__ u32 smem_u32(const void* p) {
    u32 a; asm("{ .reg .u64 t; cvta.to.shared.u64 t, %1; cvt.u32.u64 %0, t; }" : "=r"(a) : "l"(p));
    return a;
}
__device__ __forceinline__ void ldsm_x4(u32* r, u32 addr) {
    asm volatile("ldmatrix.sync.aligned.m8n8.x4.shared.b16 {%0,%1,%2,%3}, [%4];"
        : "=r"(r[0]), "=r"(r[1]), "=r"(r[2]), "=r"(r[3]) : "r"(addr));
}
__device__ __forceinline__ void mma_h(float* c, const u32* a, const u32* b) {
    asm volatile("mma.sync.aligned.m16n8k16.row.col.f32.f16.f16.f32 "
        "{%0,%1,%2,%3}, {%4,%5,%6,%7}, {%8,%9}, {%0,%1,%2,%3};"
        : "+f"(c[0]), "+f"(c[1]), "+f"(c[2]), "+f"(c[3])
        : "r"(a[0]), "r"(a[1]), "r"(a[2]), "r"(a[3]), "r"(b[0]), "r"(b[1]));
}
__device__ __forceinline__ float gelu_fast(float x) {
    float z = 1.5957691216057308f * (x + 0.044715f * x * x * x);
    return x * __frcp_rn(1.0f + __expf(-z));
}
__device__ __forceinline__ void split_pack_h(float v0, float v1, u32& hi, u32& lo) {
    __half h0 = __float2half_rn(v0), h1 = __float2half_rn(v1);
    float r0 = v0 - __half2float(h0), r1 = v1 - __half2float(h1);
    __half l0 = __float2half_rn(r0), l1 = __float2half_rn(r1);
    hi = (u32)__half_as_ushort(h0) | ((u32)__half_as_ushort(h1) << 16);
    lo = (u32)__half_as_ushort(l0) | ((u32)__half_as_ushort(l1) << 16);
}

// ---------------------------------------------------------------------------
// prep: blocks [0,512) wpack | [512,640) px | [640,2688) a
// ---------------------------------------------------------------------------
__global__ void __launch_bounds__(128) prep_kernel(const float* __restrict__ x,
                                                   const float* __restrict__ gc,
                                                   const float* __restrict__ latent,
                                                   const float* __restrict__ W0,
                                                   const float* __restrict__ b0,
                                                   const float* __restrict__ W1,
                                                   const float* __restrict__ W2) {
    int blk = blockIdx.x;
    int t = threadIdx.x;

    if (blk < 512) {                                // ---- wpack (fp16) ----
        int i = blk * 128 + t;
        if (i < 32768) {                            // W1: n 256, k 128
            int n = i >> 7, k = i & 127;
            g_W1i[n * 136 + k] = __half_as_ushort(__float2half_rn(W1[k * C1 + n]));
        } else {                                    // W2: n 128, k 256 (k-halved)
            int j = i - 32768;
            int n = j >> 8, k = j & 255;
            int kh = k >> 7, kk = k & 127;
            g_W2i[kh * 17408 + n * 136 + kk] = __half_as_ushort(__float2half_rn(W2[k * C0 + n]));
        }
        return;
    }

    __shared__ float emb[32][EMBD];
    __shared__ float ff[32][4];

    if (blk < 640) {                                // ---- px ----
        int q0 = (blk - 512) * 32;
        for (int idx = t; idx < 32 * 48; idx += 128) {
            int pt = idx / 48, rem = idx % 48;
            int c = rem >> 4, i = rem & 15;
            float coord = latent[(q0 + pt) * 3 + c];
            float sv, cv; __sincosf(coord * c_freq[i], &sv, &cv);
            emb[pt][c * 32 + i] = sv;
            emb[pt][c * 32 + 16 + i] = cv;
        }
        __syncthreads();
        float acc[32];
        float bias = b0[t];
        #pragma unroll
        for (int p = 0; p < 32; p++) acc[p] = bias;
        #pragma unroll 2
        for (int e = 0; e < EMBD; e += 4) {
            float w0 = W0[(96 + e) * C0 + t];
            float w1 = W0[(97 + e) * C0 + t];
            float w2 = W0[(98 + e) * C0 + t];
            float w3 = W0[(99 + e) * C0 + t];
            #pragma unroll
            for (int p = 0; p < 32; p++) {
                float4 ev = *(const float4*)&emb[p][e];
                acc[p] += ev.x * w0 + ev.y * w1 + ev.z * w2 + ev.w * w3;
            }
        }
        float* dst = g_Px + (size_t)q0 * C0 + t;
        #pragma unroll
        for (int p = 0; p < 32; p++) dst[p * C0] = acc[p];
        return;
    }

    // ---- a ----
    int ablk = blk - 640;
    int b = ablk >> 10;
    int j0 = (ablk & 1023) * 32;
    for (int idx = t; idx < 32 * 48; idx += 128) {
        int pt = idx / 48, rem = idx % 48;
        int c = rem >> 4, i = rem & 15;
        float coord = gc[((size_t)(b * NPTS) + j0 + pt) * 3 + c];
        float sv, cv; __sincosf(coord * c_freq[i], &sv, &cv);
        emb[pt][c * 32 + i] = sv;
        emb[pt][c * 32 + 16 + i] = cv;
    }
    {
        int pt = t >> 2, c = t & 3;
        int j = j0 + pt;
        int d = j & 31, w = (j >> 5) & 31, h = j >> 10;
        ff[pt][c] = x[(size_t)(b * 4 + c) * NPTS + (size_t)d * 1024 + h * 32 + w];
    }
    __syncthreads();
    float acc[32];
    #pragma unroll
    for (int p = 0; p < 32; p++) acc[p] = 0.0f;
    #pragma unroll 2
    for (int e = 0; e < EMBD; e += 4) {
        float w0 = W0[(e + 0) * C0 + t];
        float w1 = W0[(e + 1) * C0 + t];
        float w2 = W0[(e + 2) * C0 + t];
        float w3 = W0[(e + 3) * C0 + t];
        #pragma unroll
        for (int p = 0; p < 32; p++) {
            float4 ev = *(const float4*)&emb[p][e];
            acc[p] += ev.x * w0 + ev.y * w1 + ev.z * w2 + ev.w * w3;
        }
    }
    #pragma unroll
    for (int e = 0; e < 4; e++) {
        float w = W0[(192 + e) * C0 + t];
        #pragma unroll
        for (int p = 0; p < 32; p++) acc[p] += ff[p][e] * w;
    }
    float* dst = g_A + ((size_t)(b * NPTS + j0)) * C0 + t;
    #pragma unroll
    for (int p = 0; p < 32; p++) dst[p * C0] = acc[p];
}

// ---------------------------------------------------------------------------
// main8 — 2 queries/block (M=64), 512 threads (16 warps, 2m x 8n),
// 2 CTAs/SM, fp16 2-pass split.
// ---------------------------------------------------------------------------
__global__ void __launch_bounds__(512, 2) main8_kernel(const int* __restrict__ nbr_idx,
                                                       const unsigned int* __restrict__ nbr_mask,
                                                       const float* __restrict__ b1,
                                                       const float* __restrict__ b2,
                                                       const float* __restrict__ W3,
                                                       const float* __restrict__ b3,
                                                       float* __restrict__ out) {
    extern __shared__ char dsm_raw[];
    __shared__ int   sidx[64];
    __shared__ float smsk[64];
    __shared__ float s_hs[2][128];
    __shared__ float s_nv[2];

    u32 raw = smem_u32(dsm_raw);
    u32 base = (raw + 127u) & ~127u;
    char* dsm = dsm_raw + (base - raw);

    int t    = threadIdx.x;
    int w    = t >> 5;
    int lane = t & 31;
    int wm   = w & 1;           // rows 32*wm .. +31
    int wn   = w >> 1;          // 0..7
    int blk  = blockIdx.x;
    int b    = blk >> 11;
    int q0   = (blk & 2047) << 1;

    // ldmatrix lane offsets
    u32 aL1 = (u32)(lane & 15) * PB1 + (u32)(lane >> 4) * 16;
    u32 aL2 = (u32)(lane & 15) * PB2 + (u32)(lane >> 4) * 16;
    u32 bL1 = ((u32)(lane & 7) + (u32)((lane >> 4) << 3)) * PB1 + (u32)(((lane >> 3) & 1) << 4);

    // ---- neighbor meta + stage W1 image ----
    if (t < 64) {
        int ib = (b * NQ + q0) * KNBR + t;
        sidx[t] = nbr_idx[ib];
        smsk[t] = (nbr_mask[ib] != 0u) ? 1.0f : 0.0f;   // 4-byte bool encoding
    }
    {
        const int4* s1 = (const int4*)g_W1i;
        int4* d1 = (int4*)(dsm + OFF_W1);
        for (int i = t; i < 4352; i += 512) d1[i] = s1[i];
    }
    __syncthreads();

    // ---- phase A: gather + gelu + fp16 split into A1 (64 rows) ----
    {
        const float* Px0 = g_Px + (size_t)q0 * C0;
        #pragma unroll 2
        for (int idx = t; idx < 64 * 64; idx += 512) {
            int r = idx >> 6, cp = idx & 63;
            float2 av = *(const float2*)(g_A + ((size_t)(b * NPTS + sidx[r])) * C0 + 2 * cp);
            float2 pv = *(const float2*)(Px0 + (size_t)(r >> 5) * C0 + 2 * cp);
            float v0 = gelu_fast(av.x + pv.x);
            float v1 = gelu_fast(av.y + pv.y);
            u32 hi, lo; split_pack_h(v0, v1, hi, lo);
            u32 off = (u32)r * PB1 + (u32)cp * 4;
            *(u32*)(dsm + OFF_A1HI + off) = hi;
            *(u32*)(dsm + OFF_A1LO + off) = lo;
        }
    }
    __syncthreads();

    // ---- layer 1: warp tile 32x32, 2-pass (Ahi, Alo) x W ----
    float acc1[2][4][4] = {};   // [mi][nfrag][c]
    {
        u32 aHi = base + OFF_A1HI + (u32)(wm * 32) * PB1 + aL1;
        u32 aLo = base + OFF_A1LO + (u32)(wm * 32) * PB1 + aL1;
        u32 wB  = base + OFF_W1 + (u32)(wn * 32) * PB1 + bL1;
        for (int ks = 0; ks < 8; ks++) {
            u32 koff = ks * 32;
            u32 ah[2][4], al[2][4], bb[2][4];
            ldsm_x4(ah[0], aHi + koff);
            ldsm_x4(ah[1], aHi + 16 * PB1 + koff);
            ldsm_x4(al[0], aLo + koff);
            ldsm_x4(al[1], aLo + 16 * PB1 + koff);
            ldsm_x4(bb[0], wB + koff);
            ldsm_x4(bb[1], wB + 16 * PB1 + koff);
            #pragma unroll
            for (int nj = 0; nj < 2; nj++)
                #pragma unroll
                for (int mi = 0; mi < 2; mi++) {
                    mma_h(acc1[mi][2 * nj],     ah[mi], bb[nj]);
                    mma_h(acc1[mi][2 * nj + 1], ah[mi], bb[nj] + 2);
                }
            #pragma unroll
            for (int nj = 0; nj < 2; nj++)
                #pragma unroll
                for (int mi = 0; mi < 2; mi++) {
                    mma_h(acc1[mi][2 * nj],     al[mi], bb[nj]);
                    mma_h(acc1[mi][2 * nj + 1], al[mi], bb[nj] + 2);
                }
        }
    }
    __syncthreads();   // A1/W1 reads done; regions reused below

    // ---- epilogue 1: h1 = gelu(C1 + b1) -> A2 hi/lo ----
    {
        #pragma unroll
        for (int mi = 0; mi < 2; mi++)
            #pragma unroll
            for (int ni = 0; ni < 4; ni++) {
                const float* cc = acc1[mi][ni];
                int col = wn * 32 + ni * 8 + (lane & 3) * 2;
                int r0  = wm * 32 + mi * 16 + (lane >> 2);
                float2 bv = *(const float2*)(b1 + col);
                u32 hi, lo;
                split_pack_h(gelu_fast(cc[0] + bv.x), gelu_fast(cc[1] + bv.y), hi, lo);
                u32 off = (u32)r0 * PB2 + (u32)col * 2;
                *(u32*)(dsm + OFF_A2HI + off) = hi;
                *(u32*)(dsm + OFF_A2LO + off) = lo;
                split_pack_h(gelu_fast(cc[2] + bv.x), gelu_fast(cc[3] + bv.y), hi, lo);
                off = (u32)(r0 + 8) * PB2 + (u32)col * 2;
                *(u32*)(dsm + OFF_A2HI + off) = hi;
                *(u32*)(dsm + OFF_A2LO + off) = lo;
            }
    }

    // ---- layer 2: warp tile 32x16, K=256 via 2 staged k-halves, 2-pass ----
    float acc2[2][2][4] = {};   // [mi][nfrag][c]
    {
        u32 aHi = base + OFF_A2HI + (u32)(wm * 32) * PB2 + aL2;
        u32 aLo = base + OFF_A2LO + (u32)(wm * 32) * PB2 + aL2;
        u32 wB  = base + OFF_W2 + (u32)(wn * 16) * PB1 + bL1;
        #pragma unroll 1
        for (int kh = 0; kh < 2; kh++) {
            __syncthreads();    // A2 visible (kh=0) / prior W2 readers done (kh=1)
            {
                const int4* s1 = (const int4*)(g_W2i + kh * 17408);
                int4* d1 = (int4*)(dsm + OFF_W2);
                for (int i = t; i < 2176; i += 512) d1[i] = s1[i];
            }
            __syncthreads();
            u32 akh = (u32)kh * 256;
            for (int ks = 0; ks < 8; ks++) {
                u32 koff = ks * 32;
                u32 ah[2][4], al[2][4], bb[4];
                ldsm_x4(ah[0], aHi + akh + koff);
                ldsm_x4(ah[1], aHi + akh + 16 * PB2 + koff);
                ldsm_x4(al[0], aLo + akh + koff);
                ldsm_x4(al[1], aLo + akh + 16 * PB2 + koff);
                ldsm_x4(bb, wB + koff);
                #pragma unroll
                for (int mi = 0; mi < 2; mi++) {
                    mma_h(acc2[mi][0], ah[mi], bb);
                    mma_h(acc2[mi][1], ah[mi], bb + 2);
                }
                #pragma unroll
                for (int mi = 0; mi < 2; mi++) {
                    mma_h(acc2[mi][0], al[mi], bb);
                    mma_h(acc2[mi][1], al[mi], bb + 2);
                }
            }
        }
    }
    __syncthreads();   // A2/W2 reads done

    // ---- epilogue 2: h2 = gelu(C2 + b2) -> floats at OFF_H2 ----
    {
        float* h2 = (float*)(dsm + OFF_H2);
        #pragma unroll
        for (int mi = 0; mi < 2; mi++)
            #pragma unroll
            for (int ni = 0; ni < 2; ni++) {
                const float* cc = acc2[mi][ni];
                int col = wn * 16 + ni * 8 + (lane & 3) * 2;
                int r0  = wm * 32 + mi * 16 + (lane >> 2);
                float2 bv = *(const float2*)(b2 + col);
                *(float2*)(h2 + r0 * PH2 + col) =
                    make_float2(gelu_fast(cc[0] + bv.x), gelu_fast(cc[1] + bv.y));
                *(float2*)(h2 + (r0 + 8) * PH2 + col) =
                    make_float2(gelu_fast(cc[2] + bv.x), gelu_fast(cc[3] + bv.y));
            }
    }
    __syncthreads();

    // ---- phase D: masked row-sums (t<256: qg = t>>7, c = t&127) ----
    if (t < 256) {
        const float* h2 = (const float*)(dsm + OFF_H2);
        int c = t & 127, qg = t >> 7;
        float s = 0.0f;
        #pragma unroll
        for (int k = 0; k < 32; k++) s += smsk[qg * 32 + k] * h2[(qg * 32 + k) * PH2 + c];
        s_hs[qg][c] = s;
        if (t < 2) {
            float nv = 0.0f;
            #pragma unroll
            for (int k = 0; k < 32; k++) nv += smsk[t * 32 + k];
            s_nv[t] = nv;
        }
    }
    __syncthreads();

    // ---- phase E: out = hs @ W3 + nv*b3 (t<256) ----
    if (t < 256) {
        int c = t & 127, qg = t >> 7;
        float acc = s_nv[qg] * b3[c];
        #pragma unroll 4
        for (int j = 0; j < 128; j++) acc += s_hs[qg][j] * W3[j * C0 + c];
        int q = q0 + qg;
        int dl = q & 15, wl = (q >> 4) & 15, hl = q >> 8;
        out[((((size_t)b * 128 + c) * 16 + dl) * 16 + hl) * 16 + wl] = acc;
    }
}

extern "C" void kernel_launch(void* const* d_in, const int* in_sizes, int n_in,
                              void* d_out, int out_size) {
    const float* x        = (const float*)d_in[0];
    const float* gc       = (const float*)d_in[1];
    const float* latent   = (const float*)d_in[2];
    const int*   nbr_idx  = (const int*)d_in[3];
    const unsigned int* nbr_mask = (const unsigned int*)d_in[4];
    const float* W0 = (const float*)d_in[5];
    const float* b0 = (const float*)d_in[6];
    const float* W1 = (const float*)d_in[7];
    const float* b1 = (const float*)d_in[8];
    const float* W2 = (const float*)d_in[9];
    const float* b2 = (const float*)d_in[10];
    const float* W3 = (const float*)d_in[11];
    const float* b3 = (const float*)d_in[12];
    float* out = (float*)d_out;

    cudaFuncSetAttribute(main8_kernel, cudaFuncAttributeMaxDynamicSharedMemorySize,
                         DSM_BYTES);

    prep_kernel<<<2688, 128>>>(x, gc, latent, W0, b0, W1, W2);
    main8_kernel<<<BATCH * NQ / 2, 512, DSM_BYTES>>>(nbr_idx, nbr_mask,
                                                     b1, b2, W3, b3, out);
}

// round 16
// speedup vs baseline: 1.6646x; 1.1527x over previous
#include <cuda_runtime.h>
#include <cuda_fp16.h>
#include <math.h>

#define NPTS  32768
#define NQ    4096
#define BATCH 2
#define KNBR  32
#define EMBD  96
#define C0    128
#define C1    256

typedef unsigned int u32;
typedef unsigned short u16;

// ---------------- global scratch (no allocation allowed) ----------------
__device__ float g_A[BATCH * NPTS * C0];
__device__ float g_Px[NQ * C0];             // batch-independent (bbox == [0,1]^3)
// fp16 weight images (round-to-nearest), B-operand form [n][k], pitch k+8
__device__ __align__(16) u16 g_W1i[256 * 136];        // [n=256][k=128]
__device__ __align__(16) u16 g_W2i[2 * 128 * 136];    // [khalf][n=128][k'=128]

__constant__ float c_freq[16] = {
    1.0f, 0.562341325190349f, 0.316227766016838f, 0.177827941003892f,
    0.1f, 0.0562341325190349f, 0.0316227766016838f, 0.0177827941003892f,
    0.01f, 0.00562341325190349f, 0.00316227766016838f, 0.00177827941003892f,
    0.001f, 0.000562341325190349f, 0.000316227766016838f, 0.000177827941003892f };

// pitches (bytes)
#define PB1 272     // rows of A1/W1/W2half: 136 halves
#define PB2 528     // rows of A2: 264 halves
#define PH2 132     // h2 floats pitch

// smem regions (bytes from aligned base); peak 104448 -> 2 CTAs/SM
#define OFF_A1HI 0            // 64*272 = 17408
#define OFF_A1LO 17408        // end 34816
#define OFF_W1   34816        // 256*272 = 69632, end 104448
#define OFF_A2HI 0            // 64*528 = 33792
#define OFF_A2LO 33792        // end 67584
#define OFF_W2   67584        // 128*272 = 34816, end 102400
#define OFF_H2   0            // 64*132*4 = 33792
#define DSM_BYTES (104448 + 128)

static __device__ __forceinline__ u32 smem_u32(const void* p) {
    u32 a; asm("{ .reg .u64 t; cvta.to.shared.u64 t, %1; cvt.u32.u64 %0, t; }" : "=r"(a) : "l"(p));
    return a;
}
__device__ __forceinline__ void ldsm_x4(u32* r, u32 addr) {
    asm volatile("ldmatrix.sync.aligned.m8n8.x4.shared.b16 {%0,%1,%2,%3}, [%4];"
        : "=r"(r[0]), "=r"(r[1]), "=r"(r[2]), "=r"(r[3]) : "r"(addr));
}
__device__ __forceinline__ void mma_h(float* c, const u32* a, const u32* b) {
    asm volatile("mma.sync.aligned.m16n8k16.row.col.f32.f16.f16.f32 "
        "{%0,%1,%2,%3}, {%4,%5,%6,%7}, {%8,%9}, {%0,%1,%2,%3};"
        : "+f"(c[0]), "+f"(c[1]), "+f"(c[2]), "+f"(c[3])
        : "r"(a[0]), "r"(a[1]), "r"(a[2]), "r"(a[3]), "r"(b[0]), "r"(b[1]));
}
#define CP16(dst, src) asm volatile("cp.async.cg.shared.global [%0], [%1], 16;" :: "r"(dst), "l"(src))
#define CP_COMMIT()    asm volatile("cp.async.commit_group;" ::: "memory")
#define CP_WAIT0()     asm volatile("cp.async.wait_group 0;" ::: "memory")

__device__ __forceinline__ float gelu_fast(float x) {
    float z = 1.5957691216057308f * (x + 0.044715f * x * x * x);
    return x * __frcp_rn(1.0f + __expf(-z));
}
__device__ __forceinline__ void split_pack_h(float v0, float v1, u32& hi, u32& lo) {
    __half h0 = __float2half_rn(v0), h1 = __float2half_rn(v1);
    float r0 = v0 - __half2float(h0), r1 = v1 - __half2float(h1);
    __half l0 = __float2half_rn(r0), l1 = __float2half_rn(r1);
    hi = (u32)__half_as_ushort(h0) | ((u32)__half_as_ushort(h1) << 16);
    lo = (u32)__half_as_ushort(l0) | ((u32)__half_as_ushort(l1) << 16);
}

// ---------------------------------------------------------------------------
// prep: blocks [0,512) wpack | [512,640) px | [640,2688) a  (unchanged)
// ---------------------------------------------------------------------------
__global__ void __launch_bounds__(128) prep_kernel(const float* __restrict__ x,
                                                   const float* __restrict__ gc,
                                                   const float* __restrict__ latent,
                                                   const float* __restrict__ W0,
                                                   const float* __restrict__ b0,
                                                   const float* __restrict__ W1,
                                                   const float* __restrict__ W2) {
    int blk = blockIdx.x;
    int t = threadIdx.x;

    if (blk < 512) {                                // ---- wpack (fp16) ----
        int i = blk * 128 + t;
        if (i < 32768) {                            // W1: n 256, k 128
            int n = i >> 7, k = i & 127;
            g_W1i[n * 136 + k] = __half_as_ushort(__float2half_rn(W1[k * C1 + n]));
        } else {                                    // W2: n 128, k 256 (k-halved)
            int j = i - 32768;
            int n = j >> 8, k = j & 255;
            int kh = k >> 7, kk = k & 127;
            g_W2i[kh * 17408 + n * 136 + kk] = __half_as_ushort(__float2half_rn(W2[k * C0 + n]));
        }
        return;
    }

    __shared__ float emb[32][EMBD];
    __shared__ float ff[32][4];

    if (blk < 640) {                                // ---- px ----
        int q0 = (blk - 512) * 32;
        for (int idx = t; idx < 32 * 48; idx += 128) {
            int pt = idx / 48, rem = idx % 48;
            int c = rem >> 4, i = rem & 15;
            float coord = latent[(q0 + pt) * 3 + c];
            float sv, cv; __sincosf(coord * c_freq[i], &sv, &cv);
            emb[pt][c * 32 + i] = sv;
            emb[pt][c * 32 + 16 + i] = cv;
        }
        __syncthreads();
        float acc[32];
        float bias = b0[t];
        #pragma unroll
        for (int p = 0; p < 32; p++) acc[p] = bias;
        #pragma unroll 2
        for (int e = 0; e < EMBD; e += 4) {
            float w0 = W0[(96 + e) * C0 + t];
            float w1 = W0[(97 + e) * C0 + t];
            float w2 = W0[(98 + e) * C0 + t];
            float w3 = W0[(99 + e) * C0 + t];
            #pragma unroll
            for (int p = 0; p < 32; p++) {
                float4 ev = *(const float4*)&emb[p][e];
                acc[p] += ev.x * w0 + ev.y * w1 + ev.z * w2 + ev.w * w3;
            }
        }
        float* dst = g_Px + (size_t)q0 * C0 + t;
        #pragma unroll
        for (int p = 0; p < 32; p++) dst[p * C0] = acc[p];
        return;
    }

    // ---- a ----
    int ablk = blk - 640;
    int b = ablk >> 10;
    int j0 = (ablk & 1023) * 32;
    for (int idx = t; idx < 32 * 48; idx += 128) {
        int pt = idx / 48, rem = idx % 48;
        int c = rem >> 4, i = rem & 15;
        float coord = gc[((size_t)(b * NPTS) + j0 + pt) * 3 + c];
        float sv, cv; __sincosf(coord * c_freq[i], &sv, &cv);
        emb[pt][c * 32 + i] = sv;
        emb[pt][c * 32 + 16 + i] = cv;
    }
    {
        int pt = t >> 2, c = t & 3;
        int j = j0 + pt;
        int d = j & 31, w = (j >> 5) & 31, h = j >> 10;
        ff[pt][c] = x[(size_t)(b * 4 + c) * NPTS + (size_t)d * 1024 + h * 32 + w];
    }
    __syncthreads();
    float acc[32];
    #pragma unroll
    for (int p = 0; p < 32; p++) acc[p] = 0.0f;
    #pragma unroll 2
    for (int e = 0; e < EMBD; e += 4) {
        float w0 = W0[(e + 0) * C0 + t];
        float w1 = W0[(e + 1) * C0 + t];
        float w2 = W0[(e + 2) * C0 + t];
        float w3 = W0[(e + 3) * C0 + t];
        #pragma unroll
        for (int p = 0; p < 32; p++) {
            float4 ev = *(const float4*)&emb[p][e];
            acc[p] += ev.x * w0 + ev.y * w1 + ev.z * w2 + ev.w * w3;
        }
    }
    #pragma unroll
    for (int e = 0; e < 4; e++) {
        float w = W0[(192 + e) * C0 + t];
        #pragma unroll
        for (int p = 0; p < 32; p++) acc[p] += ff[p][e] * w;
    }
    float* dst = g_A + ((size_t)(b * NPTS + j0)) * C0 + t;
    #pragma unroll
    for (int p = 0; p < 32; p++) dst[p * C0] = acc[p];
}

// ---------------------------------------------------------------------------
// main9 — 2 queries/block, valid-row compaction (rows padded to 16),
// 512 threads (16 warps, 2m x 8n), 2 CTAs/SM, fp16 2-pass, cp.async staging.
// ---------------------------------------------------------------------------
__global__ void __launch_bounds__(512, 2) main9_kernel(const int* __restrict__ nbr_idx,
                                                       const unsigned int* __restrict__ nbr_mask,
                                                       const float* __restrict__ b1,
                                                       const float* __restrict__ b2,
                                                       const float* __restrict__ W3,
                                                       const float* __restrict__ b3,
                                                       float* __restrict__ out) {
    extern __shared__ char dsm_raw[];
    __shared__ int   s_cidx[64];
    __shared__ int   s_v[2];
    __shared__ float s_hs[2][128];

    u32 raw = smem_u32(dsm_raw);
    u32 base = (raw + 127u) & ~127u;
    char* dsm = dsm_raw + (base - raw);

    int t    = threadIdx.x;
    int w    = t >> 5;
    int lane = t & 31;
    int wm   = w & 1;           // rows 32*wm .. +31
    int wn   = w >> 1;          // 0..7
    int blk  = blockIdx.x;
    int b    = blk >> 11;
    int q0   = (blk & 2047) << 1;

    // ldmatrix lane offsets
    u32 aL1 = (u32)(lane & 15) * PB1 + (u32)(lane >> 4) * 16;
    u32 aL2 = (u32)(lane & 15) * PB2 + (u32)(lane >> 4) * 16;
    u32 bL1 = ((u32)(lane & 7) + (u32)((lane >> 4) << 3)) * PB1 + (u32)(((lane >> 3) & 1) << 4);

    // ---- stage W1 image via cp.async (overlaps meta + gather) ----
    {
        const char* src = (const char*)g_W1i;
        for (int i = t; i < 4352; i += 512)
            CP16(base + OFF_W1 + (u32)i * 16, src + (size_t)i * 16);
        CP_COMMIT();
    }

    // ---- meta: compact valid neighbor rows (warp 0) ----
    if (w == 0) {
        int ib0 = (b * NQ + q0) * KNBR + lane;
        int idx0 = nbr_idx[ib0];
        unsigned valid0 = (nbr_mask[ib0] != 0u);
        unsigned bal0 = __ballot_sync(0xffffffffu, valid0);
        int v0 = __popc(bal0);
        if (valid0) s_cidx[__popc(bal0 & ((1u << lane) - 1u))] = idx0;
        int ib1 = (b * NQ + q0 + 1) * KNBR + lane;
        int idx1 = nbr_idx[ib1];
        unsigned valid1 = (nbr_mask[ib1] != 0u);
        unsigned bal1 = __ballot_sync(0xffffffffu, valid1);
        if (valid1) s_cidx[v0 + __popc(bal1 & ((1u << lane) - 1u))] = idx1;
        if (lane == 0) { s_v[0] = v0; s_v[1] = __popc(bal1); }
    }
    __syncthreads();

    int v0 = s_v[0], v1 = s_v[1];
    int vtot = v0 + v1;
    int M16 = (vtot + 15) & ~15;
    int mtiles = M16 >> 4;                 // 0..4 m16 row-tiles
    bool act0 = (2 * wm)     < mtiles;     // this warp's first m16 tile live?
    bool act1 = (2 * wm + 1) < mtiles;

    // ---- phase A: gather compacted rows + gelu + fp16 split into A1 ----
    {
        const float* Px0 = g_Px + (size_t)q0 * C0;
        for (int idx = t; idx < (M16 << 6); idx += 512) {
            int r = idx >> 6, cp = idx & 63;
            u32 hi = 0, lo = 0;
            if (r < vtot) {
                float2 av = *(const float2*)(g_A + ((size_t)(b * NPTS + s_cidx[r])) * C0 + 2 * cp);
                const float* pxr = Px0 + ((r >= v0) ? C0 : 0) + 2 * cp;
                float f0 = gelu_fast(av.x + pxr[0]);
                float f1 = gelu_fast(av.y + pxr[1]);
                split_pack_h(f0, f1, hi, lo);
            }
            u32 off = (u32)r * PB1 + (u32)cp * 4;
            *(u32*)(dsm + OFF_A1HI + off) = hi;
            *(u32*)(dsm + OFF_A1LO + off) = lo;
        }
    }
    CP_WAIT0();
    __syncthreads();

    // ---- layer 1: warp tile 32x32 (guarded by live m16 tiles), 2-pass ----
    float acc1[2][4][4] = {};   // [mi][nfrag][c]
    if (act0) {
        u32 aHi = base + OFF_A1HI + (u32)(wm * 32) * PB1 + aL1;
        u32 aLo = base + OFF_A1LO + (u32)(wm * 32) * PB1 + aL1;
        u32 wB  = base + OFF_W1 + (u32)(wn * 32) * PB1 + bL1;
        for (int ks = 0; ks < 8; ks++) {
            u32 koff = ks * 32;
            u32 ah[2][4], al[2][4], bb[2][4];
            ldsm_x4(ah[0], aHi + koff);
            ldsm_x4(al[0], aLo + koff);
            if (act1) {
                ldsm_x4(ah[1], aHi + 16 * PB1 + koff);
                ldsm_x4(al[1], aLo + 16 * PB1 + koff);
            }
            ldsm_x4(bb[0], wB + koff);
            ldsm_x4(bb[1], wB + 16 * PB1 + koff);
            #pragma unroll
            for (int nj = 0; nj < 2; nj++) {
                mma_h(acc1[0][2 * nj],     ah[0], bb[nj]);
                mma_h(acc1[0][2 * nj + 1], ah[0], bb[nj] + 2);
                mma_h(acc1[0][2 * nj],     al[0], bb[nj]);
                mma_h(acc1[0][2 * nj + 1], al[0], bb[nj] + 2);
            }
            if (act1) {
                #pragma unroll
                for (int nj = 0; nj < 2; nj++) {
                    mma_h(acc1[1][2 * nj],     ah[1], bb[nj]);
                    mma_h(acc1[1][2 * nj + 1], ah[1], bb[nj] + 2);
                    mma_h(acc1[1][2 * nj],     al[1], bb[nj]);
                    mma_h(acc1[1][2 * nj + 1], al[1], bb[nj] + 2);
                }
            }
        }
    }
    __syncthreads();   // A1/W1 reads done; regions reused below

    // ---- stage W2 kh0 via cp.async (overlaps epilogue 1) ----
    {
        const char* src = (const char*)g_W2i;
        for (int i = t; i < 2176; i += 512)
            CP16(base + OFF_W2 + (u32)i * 16, src + (size_t)i * 16);
        CP_COMMIT();
    }

    // ---- epilogue 1: h1 = gelu(C1 + b1) -> A2 hi/lo (live tiles only) ----
    {
        #pragma unroll
        for (int mi = 0; mi < 2; mi++) {
            if ((2 * wm + mi) >= mtiles) continue;
            #pragma unroll
            for (int ni = 0; ni < 4; ni++) {
                const float* cc = acc1[mi][ni];
                int col = wn * 32 + ni * 8 + (lane & 3) * 2;
                int r0  = wm * 32 + mi * 16 + (lane >> 2);
                float2 bv = *(const float2*)(b1 + col);
                u32 hi, lo;
                split_pack_h(gelu_fast(cc[0] + bv.x), gelu_fast(cc[1] + bv.y), hi, lo);
                u32 off = (u32)r0 * PB2 + (u32)col * 2;
                *(u32*)(dsm + OFF_A2HI + off) = hi;
                *(u32*)(dsm + OFF_A2LO + off) = lo;
                split_pack_h(gelu_fast(cc[2] + bv.x), gelu_fast(cc[3] + bv.y), hi, lo);
                off = (u32)(r0 + 8) * PB2 + (u32)col * 2;
                *(u32*)(dsm + OFF_A2HI + off) = hi;
                *(u32*)(dsm + OFF_A2LO + off) = lo;
            }
        }
    }
    CP_WAIT0();
    __syncthreads();

    // ---- layer 2: warp tile 32x16, K=256 via 2 staged k-halves, 2-pass ----
    float acc2[2][2][4] = {};   // [mi][nfrag][c]
    {
        u32 aHi = base + OFF_A2HI + (u32)(wm * 32) * PB2 + aL2;
        u32 aLo = base + OFF_A2LO + (u32)(wm * 32) * PB2 + aL2;
        u32 wB  = base + OFF_W2 + (u32)(wn * 16) * PB1 + bL1;
        #pragma unroll 1
        for (int kh = 0; kh < 2; kh++) {
            if (kh == 1) {
                __syncthreads();    // kh0 W2 readers done
                const char* src = (const char*)g_W2i + 17408 * 2;
                for (int i = t; i < 2176; i += 512)
                    CP16(base + OFF_W2 + (u32)i * 16, src + (size_t)i * 16);
                CP_COMMIT();
                CP_WAIT0();
                __syncthreads();
            }
            if (act0) {
                u32 akh = (u32)kh * 256;
                for (int ks = 0; ks < 8; ks++) {
                    u32 koff = ks * 32;
                    u32 ah[2][4], al[2][4], bb[4];
                    ldsm_x4(ah[0], aHi + akh + koff);
                    ldsm_x4(al[0], aLo + akh + koff);
                    if (act1) {
                        ldsm_x4(ah[1], aHi + akh + 16 * PB2 + koff);
                        ldsm_x4(al[1], aLo + akh + 16 * PB2 + koff);
                    }
                    ldsm_x4(bb, wB + koff);
                    mma_h(acc2[0][0], ah[0], bb);
                    mma_h(acc2[0][1], ah[0], bb + 2);
                    mma_h(acc2[0][0], al[0], bb);
                    mma_h(acc2[0][1], al[0], bb + 2);
                    if (act1) {
                        mma_h(acc2[1][0], ah[1], bb);
                        mma_h(acc2[1][1], ah[1], bb + 2);
                        mma_h(acc2[1][0], al[1], bb);
                        mma_h(acc2[1][1], al[1], bb + 2);
                    }
                }
            }
        }
    }
    __syncthreads();   // A2/W2 reads done

    // ---- epilogue 2: h2 = gelu(C2 + b2) -> floats at OFF_H2 (live tiles) ----
    {
        float* h2 = (float*)(dsm + OFF_H2);
        #pragma unroll
        for (int mi = 0; mi < 2; mi++) {
            if ((2 * wm + mi) >= mtiles) continue;
            #pragma unroll
            for (int ni = 0; ni < 2; ni++) {
                const float* cc = acc2[mi][ni];
                int col = wn * 16 + ni * 8 + (lane & 3) * 2;
                int r0  = wm * 32 + mi * 16 + (lane >> 2);
                float2 bv = *(const float2*)(b2 + col);
                *(float2*)(h2 + r0 * PH2 + col) =
                    make_float2(gelu_fast(cc[0] + bv.x), gelu_fast(cc[1] + bv.y));
                *(float2*)(h2 + (r0 + 8) * PH2 + col) =
                    make_float2(gelu_fast(cc[2] + bv.x), gelu_fast(cc[3] + bv.y));
            }
        }
    }
    __syncthreads();

    // ---- phase D: per-query compacted row sums (t<256) ----
    if (t < 256) {
        const float* h2 = (const float*)(dsm + OFF_H2);
        int c = t & 127, qg = t >> 7;
        int start = qg ? v0 : 0;
        int cnt   = qg ? v1 : v0;
        float s = 0.0f;
        for (int k = 0; k < cnt; k++) s += h2[(start + k) * PH2 + c];
        s_hs[qg][c] = s;
    }
    __syncthreads();

    // ---- phase E: out = hs @ W3 + nvalid*b3 (t<256) ----
    if (t < 256) {
        int c = t & 127, qg = t >> 7;
        float nv = (float)(qg ? v1 : v0);
        float acc = nv * b3[c];
        #pragma unroll 4
        for (int j = 0; j < 128; j++) acc += s_hs[qg][j] * W3[j * C0 + c];
        int q = q0 + qg;
        int dl = q & 15, wl = (q >> 4) & 15, hl = q >> 8;
        out[((((size_t)b * 128 + c) * 16 + dl) * 16 + hl) * 16 + wl] = acc;
    }
}

extern "C" void kernel_launch(void* const* d_in, const int* in_sizes, int n_in,
                              void* d_out, int out_size) {
    const float* x        = (const float*)d_in[0];
    const float* gc       = (const float*)d_in[1];
    const float* latent   = (const float*)d_in[2];
    const int*   nbr_idx  = (const int*)d_in[3];
    const unsigned int* nbr_mask = (const unsigned int*)d_in[4];
    const float* W0 = (const float*)d_in[5];
    const float* b0 = (const float*)d_in[6];
    const float* W1 = (const float*)d_in[7];
    const float* b1 = (const float*)d_in[8];
    const float* W2 = (const float*)d_in[9];
    const float* b2 = (const float*)d_in[10];
    const float* W3 = (const float*)d_in[11];
    const float* b3 = (const float*)d_in[12];
    float* out = (float*)d_out;

    cudaFuncSetAttribute(main9_kernel, cudaFuncAttributeMaxDynamicSharedMemorySize,
                         DSM_BYTES);

    prep_kernel<<<2688, 128>>>(x, gc, latent, W0, b0, W1, W2);
    main9_kernel<<<BATCH * NQ / 2, 512, DSM_BYTES>>>(nbr_idx, nbr_mask,
                                                     b1, b2, W3, b3, out);
}

// round 17
// speedup vs baseline: 1.9125x; 1.1489x over previous
#include <cuda_runtime.h>
#include <cuda_fp16.h>
#include <math.h>

#define NPTS  32768
#define NQ    4096
#define BATCH 2
#define KNBR  32
#define EMBD  96
#define C0    128
#define C1    256

typedef unsigned int u32;
typedef unsigned short u16;

// ---------------- global scratch (no allocation allowed) ----------------
__device__ float g_A[BATCH * NPTS * C0];
__device__ float g_Px[NQ * C0];             // batch-independent (bbox == [0,1]^3)
// fp16 weight images (round-to-nearest), B-operand form [n][k], pitch k+8
__device__ __align__(16) u16 g_W1i[256 * 136];        // [n=256][k=128]
__device__ __align__(16) u16 g_W2i[2 * 128 * 136];    // [khalf][n=128][k'=128]

__constant__ float c_freq[16] = {
    1.0f, 0.562341325190349f, 0.316227766016838f, 0.177827941003892f,
    0.1f, 0.0562341325190349f, 0.0316227766016838f, 0.0177827941003892f,
    0.01f, 0.00562341325190349f, 0.00316227766016838f, 0.00177827941003892f,
    0.001f, 0.000562341325190349f, 0.000316227766016838f, 0.000177827941003892f };

// pitches (bytes)
#define PB1 272     // rows of A1/W1/W2half: 136 halves
#define PB2 528     // rows of A2: 264 halves
#define PH2 132     // h2 floats pitch

// smem regions (bytes from aligned base); peak 87040 -> 2 CTAs/SM (reg-limited)
#define OFF_A1   0            // 64*272 = 17408
#define OFF_W1   17408        // 256*272 = 69632, end 87040
#define OFF_A2   0            // 64*528 = 33792
#define OFF_W2   33792        // 128*272 = 34816, end 68608
#define OFF_H2   0            // 64*132*4 = 33792
#define DSM_BYTES (87040 + 128)

static __device__ __forceinline__ u32 smem_u32(const void* p) {
    u32 a; asm("{ .reg .u64 t; cvta.to.shared.u64 t, %1; cvt.u32.u64 %0, t; }" : "=r"(a) : "l"(p));
    return a;
}
__device__ __forceinline__ void ldsm_x4(u32* r, u32 addr) {
    asm volatile("ldmatrix.sync.aligned.m8n8.x4.shared.b16 {%0,%1,%2,%3}, [%4];"
        : "=r"(r[0]), "=r"(r[1]), "=r"(r[2]), "=r"(r[3]) : "r"(addr));
}
__device__ __forceinline__ void mma_h(float* c, const u32* a, const u32* b) {
    asm volatile("mma.sync.aligned.m16n8k16.row.col.f32.f16.f16.f32 "
        "{%0,%1,%2,%3}, {%4,%5,%6,%7}, {%8,%9}, {%0,%1,%2,%3};"
        : "+f"(c[0]), "+f"(c[1]), "+f"(c[2]), "+f"(c[3])
        : "r"(a[0]), "r"(a[1]), "r"(a[2]), "r"(a[3]), "r"(b[0]), "r"(b[1]));
}
#define CP16(dst, src) asm volatile("cp.async.cg.shared.global [%0], [%1], 16;" :: "r"(dst), "l"(src))
#define CP_COMMIT()    asm volatile("cp.async.commit_group;" ::: "memory")
#define CP_WAIT0()     asm volatile("cp.async.wait_group 0;" ::: "memory")

__device__ __forceinline__ float gelu_fast(float x) {
    float z = 1.5957691216057308f * (x + 0.044715f * x * x * x);
    return x * __frcp_rn(1.0f + __expf(-z));
}
__device__ __forceinline__ u32 pack_h(float v0, float v1) {
    __half h0 = __float2half_rn(v0), h1 = __float2half_rn(v1);
    return (u32)__half_as_ushort(h0) | ((u32)__half_as_ushort(h1) << 16);
}

// ---------------------------------------------------------------------------
// prep: blocks [0,512) wpack | [512,640) px | [640,2688) a  (unchanged)
// ---------------------------------------------------------------------------
__global__ void __launch_bounds__(128) prep_kernel(const float* __restrict__ x,
                                                   const float* __restrict__ gc,
                                                   const float* __restrict__ latent,
                                                   const float* __restrict__ W0,
                                                   const float* __restrict__ b0,
                                                   const float* __restrict__ W1,
                                                   const float* __restrict__ W2) {
    int blk = blockIdx.x;
    int t = threadIdx.x;

    if (blk < 512) {                                // ---- wpack (fp16) ----
        int i = blk * 128 + t;
        if (i < 32768) {                            // W1: n 256, k 128
            int n = i >> 7, k = i & 127;
            g_W1i[n * 136 + k] = __half_as_ushort(__float2half_rn(W1[k * C1 + n]));
        } else {                                    // W2: n 128, k 256 (k-halved)
            int j = i - 32768;
            int n = j >> 8, k = j & 255;
            int kh = k >> 7, kk = k & 127;
            g_W2i[kh * 17408 + n * 136 + kk] = __half_as_ushort(__float2half_rn(W2[k * C0 + n]));
        }
        return;
    }

    __shared__ float emb[32][EMBD];
    __shared__ float ff[32][4];

    if (blk < 640) {                                // ---- px ----
        int q0 = (blk - 512) * 32;
        for (int idx = t; idx < 32 * 48; idx += 128) {
            int pt = idx / 48, rem = idx % 48;
            int c = rem >> 4, i = rem & 15;
            float coord = latent[(q0 + pt) * 3 + c];
            float sv, cv; __sincosf(coord * c_freq[i], &sv, &cv);
            emb[pt][c * 32 + i] = sv;
            emb[pt][c * 32 + 16 + i] = cv;
        }
        __syncthreads();
        float acc[32];
        float bias = b0[t];
        #pragma unroll
        for (int p = 0; p < 32; p++) acc[p] = bias;
        #pragma unroll 2
        for (int e = 0; e < EMBD; e += 4) {
            float w0 = W0[(96 + e) * C0 + t];
            float w1 = W0[(97 + e) * C0 + t];
            float w2 = W0[(98 + e) * C0 + t];
            float w3 = W0[(99 + e) * C0 + t];
            #pragma unroll
            for (int p = 0; p < 32; p++) {
                float4 ev = *(const float4*)&emb[p][e];
                acc[p] += ev.x * w0 + ev.y * w1 + ev.z * w2 + ev.w * w3;
            }
        }
        float* dst = g_Px + (size_t)q0 * C0 + t;
        #pragma unroll
        for (int p = 0; p < 32; p++) dst[p * C0] = acc[p];
        return;
    }

    // ---- a ----
    int ablk = blk - 640;
    int b = ablk >> 10;
    int j0 = (ablk & 1023) * 32;
    for (int idx = t; idx < 32 * 48; idx += 128) {
        int pt = idx / 48, rem = idx % 48;
        int c = rem >> 4, i = rem & 15;
        float coord = gc[((size_t)(b * NPTS) + j0 + pt) * 3 + c];
        float sv, cv; __sincosf(coord * c_freq[i], &sv, &cv);
        emb[pt][c * 32 + i] = sv;
        emb[pt][c * 32 + 16 + i] = cv;
    }
    {
        int pt = t >> 2, c = t & 3;
        int j = j0 + pt;
        int d = j & 31, w = (j >> 5) & 31, h = j >> 10;
        ff[pt][c] = x[(size_t)(b * 4 + c) * NPTS + (size_t)d * 1024 + h * 32 + w];
    }
    __syncthreads();
    float acc[32];
    #pragma unroll
    for (int p = 0; p < 32; p++) acc[p] = 0.0f;
    #pragma unroll 2
    for (int e = 0; e < EMBD; e += 4) {
        float w0 = W0[(e + 0) * C0 + t];
        float w1 = W0[(e + 1) * C0 + t];
        float w2 = W0[(e + 2) * C0 + t];
        float w3 = W0[(e + 3) * C0 + t];
        #pragma unroll
        for (int p = 0; p < 32; p++) {
            float4 ev = *(const float4*)&emb[p][e];
            acc[p] += ev.x * w0 + ev.y * w1 + ev.z * w2 + ev.w * w3;
        }
    }
    #pragma unroll
    for (int e = 0; e < 4; e++) {
        float w = W0[(192 + e) * C0 + t];
        #pragma unroll
        for (int p = 0; p < 32; p++) acc[p] += ff[p][e] * w;
    }
    float* dst = g_A + ((size_t)(b * NPTS + j0)) * C0 + t;
    #pragma unroll
    for (int p = 0; p < 32; p++) dst[p * C0] = acc[p];
}

// ---------------------------------------------------------------------------
// main10 — 2 queries/block, valid-row compaction, 512 threads (2m x 8n),
// 2 CTAs/SM, SINGLE-PASS fp16 MMA, cp.async staging.
// ---------------------------------------------------------------------------
__global__ void __launch_bounds__(512, 2) main10_kernel(const int* __restrict__ nbr_idx,
                                                        const unsigned int* __restrict__ nbr_mask,
                                                        const float* __restrict__ b1,
                                                        const float* __restrict__ b2,
                                                        const float* __restrict__ W3,
                                                        const float* __restrict__ b3,
                                                        float* __restrict__ out) {
    extern __shared__ char dsm_raw[];
    __shared__ int   s_cidx[64];
    __shared__ int   s_v[2];
    __shared__ float s_hs[2][128];

    u32 raw = smem_u32(dsm_raw);
    u32 base = (raw + 127u) & ~127u;
    char* dsm = dsm_raw + (base - raw);

    int t    = threadIdx.x;
    int w    = t >> 5;
    int lane = t & 31;
    int wm   = w & 1;           // rows 32*wm .. +31
    int wn   = w >> 1;          // 0..7
    int blk  = blockIdx.x;
    int b    = blk >> 11;
    int q0   = (blk & 2047) << 1;

    // ldmatrix lane offsets
    u32 aL1 = (u32)(lane & 15) * PB1 + (u32)(lane >> 4) * 16;
    u32 aL2 = (u32)(lane & 15) * PB2 + (u32)(lane >> 4) * 16;
    u32 bL1 = ((u32)(lane & 7) + (u32)((lane >> 4) << 3)) * PB1 + (u32)(((lane >> 3) & 1) << 4);

    // ---- stage W1 image via cp.async (overlaps meta + gather) ----
    {
        const char* src = (const char*)g_W1i;
        for (int i = t; i < 4352; i += 512)
            CP16(base + OFF_W1 + (u32)i * 16, src + (size_t)i * 16);
        CP_COMMIT();
    }

    // ---- meta: compact valid neighbor rows (warp 0) ----
    if (w == 0) {
        int ib0 = (b * NQ + q0) * KNBR + lane;
        int idx0 = nbr_idx[ib0];
        unsigned valid0 = (nbr_mask[ib0] != 0u);
        unsigned bal0 = __ballot_sync(0xffffffffu, valid0);
        int v0 = __popc(bal0);
        if (valid0) s_cidx[__popc(bal0 & ((1u << lane) - 1u))] = idx0;
        int ib1 = (b * NQ + q0 + 1) * KNBR + lane;
        int idx1 = nbr_idx[ib1];
        unsigned valid1 = (nbr_mask[ib1] != 0u);
        unsigned bal1 = __ballot_sync(0xffffffffu, valid1);
        if (valid1) s_cidx[v0 + __popc(bal1 & ((1u << lane) - 1u))] = idx1;
        if (lane == 0) { s_v[0] = v0; s_v[1] = __popc(bal1); }
    }
    __syncthreads();

    int v0 = s_v[0], v1 = s_v[1];
    int vtot = v0 + v1;
    int M16 = (vtot + 15) & ~15;
    int mtiles = M16 >> 4;                 // 0..4 m16 row-tiles
    bool act0 = (2 * wm)     < mtiles;
    bool act1 = (2 * wm + 1) < mtiles;

    // ---- phase A: gather compacted rows + gelu -> fp16 A1 tile ----
    {
        const float* Px0 = g_Px + (size_t)q0 * C0;
        for (int idx = t; idx < (M16 << 6); idx += 512) {
            int r = idx >> 6, cp = idx & 63;
            u32 hv = 0;
            if (r < vtot) {
                float2 av = *(const float2*)(g_A + ((size_t)(b * NPTS + s_cidx[r])) * C0 + 2 * cp);
                const float* pxr = Px0 + ((r >= v0) ? C0 : 0) + 2 * cp;
                hv = pack_h(gelu_fast(av.x + pxr[0]), gelu_fast(av.y + pxr[1]));
            }
            *(u32*)(dsm + OFF_A1 + (u32)r * PB1 + (u32)cp * 4) = hv;
        }
    }
    CP_WAIT0();
    __syncthreads();

    // ---- layer 1: warp tile 32x32 (guarded), single-pass ----
    float acc1[2][4][4] = {};   // [mi][nfrag][c]
    if (act0) {
        u32 aB = base + OFF_A1 + (u32)(wm * 32) * PB1 + aL1;
        u32 wB = base + OFF_W1 + (u32)(wn * 32) * PB1 + bL1;
        for (int ks = 0; ks < 8; ks++) {
            u32 koff = ks * 32;
            u32 ah[2][4], bb[2][4];
            ldsm_x4(ah[0], aB + koff);
            if (act1) ldsm_x4(ah[1], aB + 16 * PB1 + koff);
            ldsm_x4(bb[0], wB + koff);
            ldsm_x4(bb[1], wB + 16 * PB1 + koff);
            #pragma unroll
            for (int nj = 0; nj < 2; nj++) {
                mma_h(acc1[0][2 * nj],     ah[0], bb[nj]);
                mma_h(acc1[0][2 * nj + 1], ah[0], bb[nj] + 2);
            }
            if (act1) {
                #pragma unroll
                for (int nj = 0; nj < 2; nj++) {
                    mma_h(acc1[1][2 * nj],     ah[1], bb[nj]);
                    mma_h(acc1[1][2 * nj + 1], ah[1], bb[nj] + 2);
                }
            }
        }
    }
    __syncthreads();   // A1/W1 reads done; regions reused below

    // ---- stage W2 kh0 via cp.async (overlaps epilogue 1) ----
    {
        const char* src = (const char*)g_W2i;
        for (int i = t; i < 2176; i += 512)
            CP16(base + OFF_W2 + (u32)i * 16, src + (size_t)i * 16);
        CP_COMMIT();
    }

    // ---- epilogue 1: h1 = gelu(C1 + b1) -> fp16 A2 (live tiles only) ----
    {
        #pragma unroll
        for (int mi = 0; mi < 2; mi++) {
            if ((2 * wm + mi) >= mtiles) continue;
            #pragma unroll
            for (int ni = 0; ni < 4; ni++) {
                const float* cc = acc1[mi][ni];
                int col = wn * 32 + ni * 8 + (lane & 3) * 2;
                int r0  = wm * 32 + mi * 16 + (lane >> 2);
                float2 bv = *(const float2*)(b1 + col);
                *(u32*)(dsm + OFF_A2 + (u32)r0 * PB2 + (u32)col * 2) =
                    pack_h(gelu_fast(cc[0] + bv.x), gelu_fast(cc[1] + bv.y));
                *(u32*)(dsm + OFF_A2 + (u32)(r0 + 8) * PB2 + (u32)col * 2) =
                    pack_h(gelu_fast(cc[2] + bv.x), gelu_fast(cc[3] + bv.y));
            }
        }
    }
    CP_WAIT0();
    __syncthreads();

    // ---- layer 2: warp tile 32x16, K=256 via 2 staged k-halves ----
    float acc2[2][2][4] = {};   // [mi][nfrag][c]
    {
        u32 aB = base + OFF_A2 + (u32)(wm * 32) * PB2 + aL2;
        u32 wB = base + OFF_W2 + (u32)(wn * 16) * PB1 + bL1;
        #pragma unroll 1
        for (int kh = 0; kh < 2; kh++) {
            if (kh == 1) {
                __syncthreads();    // kh0 W2 readers done
                const char* src = (const char*)g_W2i + 17408 * 2;
                for (int i = t; i < 2176; i += 512)
                    CP16(base + OFF_W2 + (u32)i * 16, src + (size_t)i * 16);
                CP_COMMIT();
                CP_WAIT0();
                __syncthreads();
            }
            if (act0) {
                u32 akh = (u32)kh * 256;
                for (int ks = 0; ks < 8; ks++) {
                    u32 koff = ks * 32;
                    u32 ah[2][4], bb[4];
                    ldsm_x4(ah[0], aB + akh + koff);
                    if (act1) ldsm_x4(ah[1], aB + akh + 16 * PB2 + koff);
                    ldsm_x4(bb, wB + koff);
                    mma_h(acc2[0][0], ah[0], bb);
                    mma_h(acc2[0][1], ah[0], bb + 2);
                    if (act1) {
                        mma_h(acc2[1][0], ah[1], bb);
                        mma_h(acc2[1][1], ah[1], bb + 2);
                    }
                }
            }
        }
    }
    __syncthreads();   // A2/W2 reads done

    // ---- epilogue 2: h2 = gelu(C2 + b2) -> floats at OFF_H2 (live tiles) ----
    {
        float* h2 = (float*)(dsm + OFF_H2);
        #pragma unroll
        for (int mi = 0; mi < 2; mi++) {
            if ((2 * wm + mi) >= mtiles) continue;
            #pragma unroll
            for (int ni = 0; ni < 2; ni++) {
                const float* cc = acc2[mi][ni];
                int col = wn * 16 + ni * 8 + (lane & 3) * 2;
                int r0  = wm * 32 + mi * 16 + (lane >> 2);
                float2 bv = *(const float2*)(b2 + col);
                *(float2*)(h2 + r0 * PH2 + col) =
                    make_float2(gelu_fast(cc[0] + bv.x), gelu_fast(cc[1] + bv.y));
                *(float2*)(h2 + (r0 + 8) * PH2 + col) =
                    make_float2(gelu_fast(cc[2] + bv.x), gelu_fast(cc[3] + bv.y));
            }
        }
    }
    __syncthreads();

    // ---- phase D: per-query compacted row sums (t<256) ----
    if (t < 256) {
        const float* h2 = (const float*)(dsm + OFF_H2);
        int c = t & 127, qg = t >> 7;
        int start = qg ? v0 : 0;
        int cnt   = qg ? v1 : v0;
        float s = 0.0f;
        for (int k = 0; k < cnt; k++) s += h2[(start + k) * PH2 + c];
        s_hs[qg][c] = s;
    }
    __syncthreads();

    // ---- phase E: out = hs @ W3 + nvalid*b3 (t<256) ----
    if (t < 256) {
        int c = t & 127, qg = t >> 7;
        float nv = (float)(qg ? v1 : v0);
        float acc = nv * b3[c];
        #pragma unroll 4
        for (int j = 0; j < 128; j++) acc += s_hs[qg][j] * W3[j * C0 + c];
        int q = q0 + qg;
        int dl = q & 15, wl = (q >> 4) & 15, hl = q >> 8;
        out[((((size_t)b * 128 + c) * 16 + dl) * 16 + hl) * 16 + wl] = acc;
    }
}

extern "C" void kernel_launch(void* const* d_in, const int* in_sizes, int n_in,
                              void* d_out, int out_size) {
    const float* x        = (const float*)d_in[0];
    const float* gc       = (const float*)d_in[1];
    const float* latent   = (const float*)d_in[2];
    const int*   nbr_idx  = (const int*)d_in[3];
    const unsigned int* nbr_mask = (const unsigned int*)d_in[4];
    const float* W0 = (const float*)d_in[5];
    const float* b0 = (const float*)d_in[6];
    const float* W1 = (const float*)d_in[7];
    const float* b1 = (const float*)d_in[8];
    const float* W2 = (const float*)d_in[9];
    const float* b2 = (const float*)d_in[10];
    const float* W3 = (const float*)d_in[11];
    const float* b3 = (const float*)d_in[12];
    float* out = (float*)d_out;

    cudaFuncSetAttribute(main10_kernel, cudaFuncAttributeMaxDynamicSharedMemorySize,
                         DSM_BYTES);

    prep_kernel<<<2688, 128>>>(x, gc, latent, W0, b0, W1, W2);
    main10_kernel<<<BATCH * NQ / 2, 512, DSM_BYTES>>>(nbr_idx, nbr_mask,
                                                      b1, b2, W3, b3, out);
}